// round 2
// baseline (speedup 1.0000x reference)
#include <cuda_runtime.h>
#include <cstdint>

// Problem constants
#define Bb 2
#define Ss 2048
#define Ee 1024
#define Hh 16
#define Dd 64
#define MM (Bb * Ss)   // 4096 rows

// Scratch buffers (device globals — no cudaMalloc allowed)
__device__ float g_Q[MM * Ee];
__device__ float g_K[MM * Ee];
__device__ float g_V[MM * Ee];
__device__ float g_A[MM * Ee];

// ---------------------------------------------------------------------------
// SGEMM with bias: C[M,N] = A[M,K] @ W[K,N] + bias[N]
// BM=128, BN=128, BK=16, TM=TN=8, 256 threads. M,N,K multiples of tile sizes.
// ---------------------------------------------------------------------------
__global__ __launch_bounds__(256) void gemm_bias_kernel(
    const float* __restrict__ A, const float* __restrict__ W,
    const float* __restrict__ bias, float* __restrict__ C,
    int M, int N, int K)
{
    constexpr int BM = 128, BN = 128, BK = 16, TM = 8, TN = 8;
    __shared__ float As[BK][BM];
    __shared__ float Bs[BK][BN];

    const int tid = threadIdx.x;
    const int tx = tid & 15;        // 0..15 -> column group
    const int ty = tid >> 4;        // 0..15 -> row group
    const int row0 = blockIdx.y * BM;
    const int col0 = blockIdx.x * BN;

    float acc[TM][TN];
    #pragma unroll
    for (int i = 0; i < TM; i++)
        #pragma unroll
        for (int j = 0; j < TN; j++) acc[i][j] = 0.f;

    for (int k0 = 0; k0 < K; k0 += BK) {
        // Load A tile (BM x BK) transposed into As[BK][BM].
        // 128 rows * 4 float4 = 512 float4; 256 threads -> 2 each.
        #pragma unroll
        for (int it = 0; it < 2; it++) {
            int idx = tid + it * 256;        // 0..511
            int r = idx >> 2;                // 0..127
            int c4 = idx & 3;                // float4 within row
            float4 a = *(const float4*)(A + (size_t)(row0 + r) * K + k0 + c4 * 4);
            As[c4 * 4 + 0][r] = a.x;
            As[c4 * 4 + 1][r] = a.y;
            As[c4 * 4 + 2][r] = a.z;
            As[c4 * 4 + 3][r] = a.w;
        }
        // Load W tile (BK x BN) straight: 16 rows * 32 float4 = 512 float4.
        #pragma unroll
        for (int it = 0; it < 2; it++) {
            int idx = tid + it * 256;
            int r = idx >> 5;                // 0..15
            int c4 = idx & 31;               // 0..31
            *(float4*)(&Bs[r][c4 * 4]) =
                *(const float4*)(W + (size_t)(k0 + r) * N + col0 + c4 * 4);
        }
        __syncthreads();

        #pragma unroll
        for (int kk = 0; kk < BK; kk++) {
            float aReg[TM], bReg[TN];
            #pragma unroll
            for (int i = 0; i < TM; i++) aReg[i] = As[kk][ty * TM + i];
            #pragma unroll
            for (int j = 0; j < TN; j++) bReg[j] = Bs[kk][tx * TN + j];
            #pragma unroll
            for (int i = 0; i < TM; i++)
                #pragma unroll
                for (int j = 0; j < TN; j++)
                    acc[i][j] += aReg[i] * bReg[j];
        }
        __syncthreads();
    }

    // Epilogue: add bias, vectorized stores
    #pragma unroll
    for (int i = 0; i < TM; i++) {
        int r = row0 + ty * TM + i;
        #pragma unroll
        for (int j4 = 0; j4 < TN / 4; j4++) {
            int c = col0 + tx * TN + j4 * 4;
            float4 v;
            v.x = acc[i][j4 * 4 + 0] + bias[c + 0];
            v.y = acc[i][j4 * 4 + 1] + bias[c + 1];
            v.z = acc[i][j4 * 4 + 2] + bias[c + 2];
            v.w = acc[i][j4 * 4 + 3] + bias[c + 3];
            *(float4*)(C + (size_t)r * N + c) = v;
        }
    }
}

// ---------------------------------------------------------------------------
// Causal attention, fp32, flash-style. One thread = one query row.
// Block: 128 threads (128 queries). K/V staged in SMEM, 64 keys per tile.
// grid = (S/128, B*H)
// ---------------------------------------------------------------------------
__global__ __launch_bounds__(128, 2) void attn_kernel(
    const float* __restrict__ Q, const float* __restrict__ K,
    const float* __restrict__ V, float* __restrict__ O)
{
    constexpr int BQ = 128, BKEY = 64;
    __shared__ float Ks[BKEY][Dd];
    __shared__ float Vs[BKEY][Dd];

    const int bh = blockIdx.y;
    const int b = bh >> 4;           // / H
    const int h = bh & 15;           // % H
    const int q = blockIdx.x * BQ + threadIdx.x;

    const float* qptr = Q + ((size_t)(b * Ss + q)) * Ee + h * Dd;
    float4 qreg[16];
    #pragma unroll
    for (int i = 0; i < 16; i++) qreg[i] = *(const float4*)(qptr + i * 4);

    float4 o4[16];
    #pragma unroll
    for (int i = 0; i < 16; i++) o4[i] = make_float4(0.f, 0.f, 0.f, 0.f);
    float m = -1e30f, l = 0.f;

    const int ntiles = 2 * blockIdx.x + 2;   // keys up to blockIdx.x*128+127
    const float* kbase = K + ((size_t)(b * Ss)) * Ee + h * Dd;
    const float* vbase = V + ((size_t)(b * Ss)) * Ee + h * Dd;

    for (int kt = 0; kt < ntiles; kt++) {
        __syncthreads();
        // cooperative tile load: 64 rows x 16 float4 each for K and V
        #pragma unroll
        for (int it = 0; it < 8; it++) {
            int idx = threadIdx.x + it * 128;   // 0..1023
            int r = idx >> 4;
            int c = idx & 15;
            size_t goff = (size_t)(kt * BKEY + r) * Ee + c * 4;
            ((float4*)Ks[r])[c] = *(const float4*)(kbase + goff);
            ((float4*)Vs[r])[c] = *(const float4*)(vbase + goff);
        }
        __syncthreads();

        #pragma unroll 1
        for (int j0 = 0; j0 < BKEY; j0 += 8) {
            float s[8];
            #pragma unroll
            for (int jj = 0; jj < 8; jj++) {
                const float4* krow = (const float4*)Ks[j0 + jj];
                float4 a = make_float4(0.f, 0.f, 0.f, 0.f);
                #pragma unroll
                for (int i = 0; i < 16; i++) {
                    float4 kv = krow[i];
                    a.x += qreg[i].x * kv.x;
                    a.y += qreg[i].y * kv.y;
                    a.z += qreg[i].z * kv.z;
                    a.w += qreg[i].w * kv.w;
                }
                float sc = (a.x + a.y + a.z + a.w) * 0.125f;
                int key = kt * BKEY + j0 + jj;
                s[jj] = (key > q) ? -10000.0f : sc;   // exact reference masking
            }
            float mt = m;
            #pragma unroll
            for (int jj = 0; jj < 8; jj++) mt = fmaxf(mt, s[jj]);
            float scale = __expf(m - mt);
            float p[8];
            float ps = 0.f;
            #pragma unroll
            for (int jj = 0; jj < 8; jj++) { p[jj] = __expf(s[jj] - mt); ps += p[jj]; }
            l = l * scale + ps;
            m = mt;
            #pragma unroll
            for (int i = 0; i < 16; i++) {
                o4[i].x *= scale; o4[i].y *= scale; o4[i].z *= scale; o4[i].w *= scale;
            }
            #pragma unroll
            for (int jj = 0; jj < 8; jj++) {
                const float4* vrow = (const float4*)Vs[j0 + jj];
                float pj = p[jj];
                #pragma unroll
                for (int i = 0; i < 16; i++) {
                    float4 vv = vrow[i];
                    o4[i].x += pj * vv.x;
                    o4[i].y += pj * vv.y;
                    o4[i].z += pj * vv.z;
                    o4[i].w += pj * vv.w;
                }
            }
        }
    }

    const float inv = 1.f / l;
    float* optr = O + ((size_t)(b * Ss + q)) * Ee + h * Dd;
    #pragma unroll
    for (int i = 0; i < 16; i++) {
        float4 v;
        v.x = o4[i].x * inv; v.y = o4[i].y * inv;
        v.z = o4[i].z * inv; v.w = o4[i].w * inv;
        *(float4*)(optr + i * 4) = v;
    }
}

// ---------------------------------------------------------------------------
extern "C" void kernel_launch(void* const* d_in, const int* in_sizes, int n_in,
                              void* d_out, int out_size)
{
    const float* x  = (const float*)d_in[0];
    const float* Wq = (const float*)d_in[1];
    const float* bq = (const float*)d_in[2];
    const float* Wk = (const float*)d_in[3];
    const float* bk = (const float*)d_in[4];
    const float* Wv = (const float*)d_in[5];
    const float* bv = (const float*)d_in[6];
    const float* Wo = (const float*)d_in[7];
    const float* bo = (const float*)d_in[8];
    float* out = (float*)d_out;

    float *Qb, *Kb, *Vb, *Ab;
    cudaGetSymbolAddress((void**)&Qb, g_Q);
    cudaGetSymbolAddress((void**)&Kb, g_K);
    cudaGetSymbolAddress((void**)&Vb, g_V);
    cudaGetSymbolAddress((void**)&Ab, g_A);

    dim3 gemmGrid(Ee / 128, MM / 128);   // (8, 32)
    dim3 gemmBlk(256);

    gemm_bias_kernel<<<gemmGrid, gemmBlk>>>(x, Wq, bq, Qb, MM, Ee, Ee);
    gemm_bias_kernel<<<gemmGrid, gemmBlk>>>(x, Wk, bk, Kb, MM, Ee, Ee);
    gemm_bias_kernel<<<gemmGrid, gemmBlk>>>(x, Wv, bv, Vb, MM, Ee, Ee);

    dim3 attnGrid(Ss / 128, Bb * Hh);    // (16, 32)
    attn_kernel<<<attnGrid, 128>>>(Qb, Kb, Vb, Ab);

    gemm_bias_kernel<<<gemmGrid, gemmBlk>>>(Ab, Wo, bo, out, MM, Ee, Ee);
}

// round 3
// speedup vs baseline: 1.3526x; 1.3526x over previous
#include <cuda_runtime.h>
#include <cuda_bf16.h>
#include <cstdint>

// Problem constants
#define Bb 2
#define Ss 2048
#define Ee 1024
#define Hh 16
#define Dd 64
#define MM (Bb * Ss)   // 4096 rows

// Scratch buffers (device globals — no cudaMalloc allowed)
__device__ float g_Q[MM * Ee];
__device__ float g_K[MM * Ee];
__device__ float g_V[MM * Ee];
__device__ float g_A[MM * Ee];

// ---------------------------------------------------------------------------
// PTX helpers
// ---------------------------------------------------------------------------
__device__ __forceinline__ uint32_t smem_u32(const void* p) {
    return (uint32_t)__cvta_generic_to_shared(p);
}

__device__ __forceinline__ void ldsm4(uint32_t* r, uint32_t addr) {
    asm volatile("ldmatrix.sync.aligned.m8n8.x4.shared.b16 {%0,%1,%2,%3}, [%4];"
                 : "=r"(r[0]), "=r"(r[1]), "=r"(r[2]), "=r"(r[3]) : "r"(addr));
}

__device__ __forceinline__ void ldsm4t(uint32_t* r, uint32_t addr) {
    asm volatile("ldmatrix.sync.aligned.m8n8.x4.trans.shared.b16 {%0,%1,%2,%3}, [%4];"
                 : "=r"(r[0]), "=r"(r[1]), "=r"(r[2]), "=r"(r[3]) : "r"(addr));
}

__device__ __forceinline__ void mma_bf16(float* c, const uint32_t* a, const uint32_t* b) {
    asm volatile(
        "mma.sync.aligned.m16n8k16.row.col.f32.bf16.bf16.f32 "
        "{%0,%1,%2,%3}, {%4,%5,%6,%7}, {%8,%9}, {%0,%1,%2,%3};"
        : "+f"(c[0]), "+f"(c[1]), "+f"(c[2]), "+f"(c[3])
        : "r"(a[0]), "r"(a[1]), "r"(a[2]), "r"(a[3]), "r"(b[0]), "r"(b[1]));
}

__device__ __forceinline__ __nv_bfloat162 split_hi(float x0, float x1) {
    return __nv_bfloat162(__float2bfloat16(x0), __float2bfloat16(x1));
}
__device__ __forceinline__ __nv_bfloat162 split_lo(float x0, float x1) {
    float h0 = __bfloat162float(__float2bfloat16(x0));
    float h1 = __bfloat162float(__float2bfloat16(x1));
    return __nv_bfloat162(__float2bfloat16(x0 - h0), __float2bfloat16(x1 - h1));
}

// ---------------------------------------------------------------------------
// bf16x3 emulated-fp32 GEMM with bias: C[M,N] = A[M,K] @ W[K,N] + bias[N]
// C = Ahi*Bhi + Ahi*Blo + Alo*Bhi  (fp32 accumulate) — error ~2^-16.
// BM=128, BN=128, BK=32. 256 threads = 8 warps (4 m x 2 n), warp tile 32x64.
// M,N,K multiples of tile sizes (4096/1024/1024 here).
// ---------------------------------------------------------------------------
__global__ __launch_bounds__(256) void gemm_bias_tc_kernel(
    const float* __restrict__ A, const float* __restrict__ W,
    const float* __restrict__ bias, float* __restrict__ C,
    int M, int N, int K)
{
    constexpr int BM = 128, BN = 128, BK = 32;
    constexpr int ASTR = BK + 8;    // 40 bf16 (80B, 16B-aligned rows, conflict-free ldmatrix)
    constexpr int BSTR = BN + 8;    // 136 bf16 (272B rows)

    __shared__ __nv_bfloat16 Ahi[BM][ASTR];
    __shared__ __nv_bfloat16 Alo[BM][ASTR];
    __shared__ __nv_bfloat16 Bhi[BK][BSTR];
    __shared__ __nv_bfloat16 Blo[BK][BSTR];

    const int tid  = threadIdx.x;
    const int lane = tid & 31;
    const int wid  = tid >> 5;
    const int warp_m = wid & 3;     // 0..3  -> 32-row slab
    const int warp_n = wid >> 2;    // 0..1  -> 64-col slab
    const int row0 = blockIdx.y * BM;
    const int col0 = blockIdx.x * BN;

    // Global-load assignment
    const int ar = tid >> 1;            // A row 0..127
    const int ac = (tid & 1) * 16;      // A col group (16 floats)
    const int br = tid >> 3;            // B row 0..31
    const int bc = (tid & 7) * 16;      // B col group (16 floats)

    float4 aReg[4], bReg[4];
    const float* aPtr = A + (size_t)(row0 + ar) * K + ac;
    const float* bPtr = W + (size_t)br * N + col0 + bc;

    // prefetch tile 0
    #pragma unroll
    for (int i = 0; i < 4; i++) aReg[i] = *(const float4*)(aPtr + i * 4);
    #pragma unroll
    for (int i = 0; i < 4; i++) bReg[i] = *(const float4*)(bPtr + i * 4);

    float acc[2][8][4];
    #pragma unroll
    for (int mt = 0; mt < 2; mt++)
        #pragma unroll
        for (int j = 0; j < 8; j++)
            #pragma unroll
            for (int r = 0; r < 4; r++) acc[mt][j][r] = 0.f;

    // ldmatrix SMEM addresses (same lane pattern for A and B-trans)
    const int lrow = lane & 15;
    const int lcol8 = (lane >> 4) * 8;

    const int nTiles = K / BK;
    for (int kt = 0; kt < nTiles; kt++) {
        // convert + store current tile to SMEM
        #pragma unroll
        for (int i = 0; i < 4; i++) {
            float4 v = aReg[i];
            *(__nv_bfloat162*)(&Ahi[ar][ac + i * 4 + 0]) = split_hi(v.x, v.y);
            *(__nv_bfloat162*)(&Ahi[ar][ac + i * 4 + 2]) = split_hi(v.z, v.w);
            *(__nv_bfloat162*)(&Alo[ar][ac + i * 4 + 0]) = split_lo(v.x, v.y);
            *(__nv_bfloat162*)(&Alo[ar][ac + i * 4 + 2]) = split_lo(v.z, v.w);
        }
        #pragma unroll
        for (int i = 0; i < 4; i++) {
            float4 v = bReg[i];
            *(__nv_bfloat162*)(&Bhi[br][bc + i * 4 + 0]) = split_hi(v.x, v.y);
            *(__nv_bfloat162*)(&Bhi[br][bc + i * 4 + 2]) = split_hi(v.z, v.w);
            *(__nv_bfloat162*)(&Blo[br][bc + i * 4 + 0]) = split_lo(v.x, v.y);
            *(__nv_bfloat162*)(&Blo[br][bc + i * 4 + 2]) = split_lo(v.z, v.w);
        }
        __syncthreads();

        // prefetch next tile (overlaps with mma compute below)
        if (kt + 1 < nTiles) {
            const float* aN = aPtr + (kt + 1) * BK;
            const float* bN = bPtr + (size_t)(kt + 1) * BK * N;
            #pragma unroll
            for (int i = 0; i < 4; i++) aReg[i] = *(const float4*)(aN + i * 4);
            #pragma unroll
            for (int i = 0; i < 4; i++) bReg[i] = *(const float4*)(bN + i * 4);
        }

        // compute: 2 k16 steps
        #pragma unroll
        for (int ks = 0; ks < 2; ks++) {
            uint32_t ah[2][4], al[2][4];
            #pragma unroll
            for (int mt = 0; mt < 2; mt++) {
                int r = warp_m * 32 + mt * 16 + lrow;
                int c = ks * 16 + lcol8;
                ldsm4(ah[mt], smem_u32(&Ahi[r][c]));
                ldsm4(al[mt], smem_u32(&Alo[r][c]));
            }
            uint32_t bh[4][4], bl[4][4];
            #pragma unroll
            for (int g = 0; g < 4; g++) {
                int r = ks * 16 + lrow;
                int c = warp_n * 64 + g * 16 + lcol8;
                ldsm4t(bh[g], smem_u32(&Bhi[r][c]));
                ldsm4t(bl[g], smem_u32(&Blo[r][c]));
            }
            #pragma unroll
            for (int mt = 0; mt < 2; mt++) {
                #pragma unroll
                for (int g = 0; g < 4; g++) {
                    // n8 tile 2g   uses b regs {0,1}; tile 2g+1 uses {2,3}
                    mma_bf16(acc[mt][2 * g],     ah[mt], &bh[g][0]);
                    mma_bf16(acc[mt][2 * g],     ah[mt], &bl[g][0]);
                    mma_bf16(acc[mt][2 * g],     al[mt], &bh[g][0]);
                    mma_bf16(acc[mt][2 * g + 1], ah[mt], &bh[g][2]);
                    mma_bf16(acc[mt][2 * g + 1], ah[mt], &bl[g][2]);
                    mma_bf16(acc[mt][2 * g + 1], al[mt], &bh[g][2]);
                }
            }
        }
        __syncthreads();
    }

    // Epilogue: c frag layout c0,c1 -> (row=lane>>2, col=(lane&3)*2), c2,c3 -> row+8
    const int erow = row0 + warp_m * 32 + (lane >> 2);
    const int ecol = col0 + warp_n * 64 + (lane & 3) * 2;
    #pragma unroll
    for (int mt = 0; mt < 2; mt++) {
        #pragma unroll
        for (int j = 0; j < 8; j++) {
            int c = ecol + j * 8;
            float b0 = bias[c], b1 = bias[c + 1];
            int r = erow + mt * 16;
            float2 v0 = make_float2(acc[mt][j][0] + b0, acc[mt][j][1] + b1);
            float2 v1 = make_float2(acc[mt][j][2] + b0, acc[mt][j][3] + b1);
            *(float2*)(C + (size_t)r * N + c) = v0;
            *(float2*)(C + (size_t)(r + 8) * N + c) = v1;
        }
    }
}

// ---------------------------------------------------------------------------
// Causal attention, fp32, flash-style. One thread = one query row.
// Block: 128 threads (128 queries). K/V staged in SMEM, 64 keys per tile.
// grid = (S/128, B*H)
// ---------------------------------------------------------------------------
__global__ __launch_bounds__(128, 2) void attn_kernel(
    const float* __restrict__ Q, const float* __restrict__ K,
    const float* __restrict__ V, float* __restrict__ O)
{
    constexpr int BQ = 128, BKEY = 64;
    __shared__ float Ks[BKEY][Dd];
    __shared__ float Vs[BKEY][Dd];

    const int bh = blockIdx.y;
    const int b = bh >> 4;           // / H
    const int h = bh & 15;           // % H
    const int q = blockIdx.x * BQ + threadIdx.x;

    const float* qptr = Q + ((size_t)(b * Ss + q)) * Ee + h * Dd;
    float4 qreg[16];
    #pragma unroll
    for (int i = 0; i < 16; i++) qreg[i] = *(const float4*)(qptr + i * 4);

    float4 o4[16];
    #pragma unroll
    for (int i = 0; i < 16; i++) o4[i] = make_float4(0.f, 0.f, 0.f, 0.f);
    float m = -1e30f, l = 0.f;

    const int ntiles = 2 * blockIdx.x + 2;
    const float* kbase = K + ((size_t)(b * Ss)) * Ee + h * Dd;
    const float* vbase = V + ((size_t)(b * Ss)) * Ee + h * Dd;

    for (int kt = 0; kt < ntiles; kt++) {
        __syncthreads();
        #pragma unroll
        for (int it = 0; it < 8; it++) {
            int idx = threadIdx.x + it * 128;
            int r = idx >> 4;
            int c = idx & 15;
            size_t goff = (size_t)(kt * BKEY + r) * Ee + c * 4;
            ((float4*)Ks[r])[c] = *(const float4*)(kbase + goff);
            ((float4*)Vs[r])[c] = *(const float4*)(vbase + goff);
        }
        __syncthreads();

        #pragma unroll 1
        for (int j0 = 0; j0 < BKEY; j0 += 8) {
            float s[8];
            #pragma unroll
            for (int jj = 0; jj < 8; jj++) {
                const float4* krow = (const float4*)Ks[j0 + jj];
                float4 a = make_float4(0.f, 0.f, 0.f, 0.f);
                #pragma unroll
                for (int i = 0; i < 16; i++) {
                    float4 kv = krow[i];
                    a.x += qreg[i].x * kv.x;
                    a.y += qreg[i].y * kv.y;
                    a.z += qreg[i].z * kv.z;
                    a.w += qreg[i].w * kv.w;
                }
                float sc = (a.x + a.y + a.z + a.w) * 0.125f;
                int key = kt * BKEY + j0 + jj;
                s[jj] = (key > q) ? -10000.0f : sc;
            }
            float mt = m;
            #pragma unroll
            for (int jj = 0; jj < 8; jj++) mt = fmaxf(mt, s[jj]);
            float scale = __expf(m - mt);
            float p[8];
            float ps = 0.f;
            #pragma unroll
            for (int jj = 0; jj < 8; jj++) { p[jj] = __expf(s[jj] - mt); ps += p[jj]; }
            l = l * scale + ps;
            m = mt;
            #pragma unroll
            for (int i = 0; i < 16; i++) {
                o4[i].x *= scale; o4[i].y *= scale; o4[i].z *= scale; o4[i].w *= scale;
            }
            #pragma unroll
            for (int jj = 0; jj < 8; jj++) {
                const float4* vrow = (const float4*)Vs[j0 + jj];
                float pj = p[jj];
                #pragma unroll
                for (int i = 0; i < 16; i++) {
                    float4 vv = vrow[i];
                    o4[i].x += pj * vv.x;
                    o4[i].y += pj * vv.y;
                    o4[i].z += pj * vv.z;
                    o4[i].w += pj * vv.w;
                }
            }
        }
    }

    const float inv = 1.f / l;
    float* optr = O + ((size_t)(b * Ss + q)) * Ee + h * Dd;
    #pragma unroll
    for (int i = 0; i < 16; i++) {
        float4 v;
        v.x = o4[i].x * inv; v.y = o4[i].y * inv;
        v.z = o4[i].z * inv; v.w = o4[i].w * inv;
        *(float4*)(optr + i * 4) = v;
    }
}

// ---------------------------------------------------------------------------
extern "C" void kernel_launch(void* const* d_in, const int* in_sizes, int n_in,
                              void* d_out, int out_size)
{
    const float* x  = (const float*)d_in[0];
    const float* Wq = (const float*)d_in[1];
    const float* bq = (const float*)d_in[2];
    const float* Wk = (const float*)d_in[3];
    const float* bk = (const float*)d_in[4];
    const float* Wv = (const float*)d_in[5];
    const float* bv = (const float*)d_in[6];
    const float* Wo = (const float*)d_in[7];
    const float* bo = (const float*)d_in[8];
    float* out = (float*)d_out;

    float *Qb, *Kb, *Vb, *Ab;
    cudaGetSymbolAddress((void**)&Qb, g_Q);
    cudaGetSymbolAddress((void**)&Kb, g_K);
    cudaGetSymbolAddress((void**)&Vb, g_V);
    cudaGetSymbolAddress((void**)&Ab, g_A);

    dim3 gemmGrid(Ee / 128, MM / 128);   // (8, 32)
    dim3 gemmBlk(256);

    gemm_bias_tc_kernel<<<gemmGrid, gemmBlk>>>(x, Wq, bq, Qb, MM, Ee, Ee);
    gemm_bias_tc_kernel<<<gemmGrid, gemmBlk>>>(x, Wk, bk, Kb, MM, Ee, Ee);
    gemm_bias_tc_kernel<<<gemmGrid, gemmBlk>>>(x, Wv, bv, Vb, MM, Ee, Ee);

    dim3 attnGrid(Ss / 128, Bb * Hh);    // (16, 32)
    attn_kernel<<<attnGrid, 128>>>(Qb, Kb, Vb, Ab);

    gemm_bias_tc_kernel<<<gemmGrid, gemmBlk>>>(Ab, Wo, bo, out, MM, Ee, Ee);
}

// round 4
// speedup vs baseline: 2.6467x; 1.9568x over previous
#include <cuda_runtime.h>
#include <cuda_bf16.h>
#include <cstdint>

// Problem constants
#define Bb 2
#define Ss 2048
#define Ee 1024
#define Hh 16
#define Dd 64
#define MM (Bb * Ss)   // 4096 rows

// Scratch buffers (device globals — no cudaMalloc allowed)
__device__ float g_Q[MM * Ee];
__device__ float g_K[MM * Ee];
__device__ float g_V[MM * Ee];
__device__ float g_A[MM * Ee];

// ---------------------------------------------------------------------------
// PTX helpers
// ---------------------------------------------------------------------------
__device__ __forceinline__ uint32_t smem_u32(const void* p) {
    return (uint32_t)__cvta_generic_to_shared(p);
}

__device__ __forceinline__ void ldsm4(uint32_t* r, uint32_t addr) {
    asm volatile("ldmatrix.sync.aligned.m8n8.x4.shared.b16 {%0,%1,%2,%3}, [%4];"
                 : "=r"(r[0]), "=r"(r[1]), "=r"(r[2]), "=r"(r[3]) : "r"(addr));
}

__device__ __forceinline__ void ldsm4t(uint32_t* r, uint32_t addr) {
    asm volatile("ldmatrix.sync.aligned.m8n8.x4.trans.shared.b16 {%0,%1,%2,%3}, [%4];"
                 : "=r"(r[0]), "=r"(r[1]), "=r"(r[2]), "=r"(r[3]) : "r"(addr));
}

__device__ __forceinline__ void mma_bf16(float* c, const uint32_t* a, const uint32_t* b) {
    asm volatile(
        "mma.sync.aligned.m16n8k16.row.col.f32.bf16.bf16.f32 "
        "{%0,%1,%2,%3}, {%4,%5,%6,%7}, {%8,%9}, {%0,%1,%2,%3};"
        : "+f"(c[0]), "+f"(c[1]), "+f"(c[2]), "+f"(c[3])
        : "r"(a[0]), "r"(a[1]), "r"(a[2]), "r"(a[3]), "r"(b[0]), "r"(b[1]));
}

__device__ __forceinline__ void mma_b2(float* c, const uint32_t* a, uint32_t b0, uint32_t b1) {
    asm volatile(
        "mma.sync.aligned.m16n8k16.row.col.f32.bf16.bf16.f32 "
        "{%0,%1,%2,%3}, {%4,%5,%6,%7}, {%8,%9}, {%0,%1,%2,%3};"
        : "+f"(c[0]), "+f"(c[1]), "+f"(c[2]), "+f"(c[3])
        : "r"(a[0]), "r"(a[1]), "r"(a[2]), "r"(a[3]), "r"(b0), "r"(b1));
}

__device__ __forceinline__ __nv_bfloat162 split_hi(float x0, float x1) {
    return __nv_bfloat162(__float2bfloat16(x0), __float2bfloat16(x1));
}
__device__ __forceinline__ __nv_bfloat162 split_lo(float x0, float x1) {
    float h0 = __bfloat162float(__float2bfloat16(x0));
    float h1 = __bfloat162float(__float2bfloat16(x1));
    return __nv_bfloat162(__float2bfloat16(x0 - h0), __float2bfloat16(x1 - h1));
}
__device__ __forceinline__ uint32_t pack_hi(float x0, float x1) {
    __nv_bfloat162 t = split_hi(x0, x1);
    return *(uint32_t*)&t;
}
__device__ __forceinline__ uint32_t pack_lo(float x0, float x1) {
    __nv_bfloat162 t = split_lo(x0, x1);
    return *(uint32_t*)&t;
}

// ---------------------------------------------------------------------------
// bf16x3 emulated-fp32 GEMM with bias (unchanged from R2)
// ---------------------------------------------------------------------------
__global__ __launch_bounds__(256) void gemm_bias_tc_kernel(
    const float* __restrict__ A, const float* __restrict__ W,
    const float* __restrict__ bias, float* __restrict__ C,
    int M, int N, int K)
{
    constexpr int BM = 128, BN = 128, BK = 32;
    constexpr int ASTR = BK + 8;
    constexpr int BSTR = BN + 8;

    __shared__ __nv_bfloat16 Ahi[BM][ASTR];
    __shared__ __nv_bfloat16 Alo[BM][ASTR];
    __shared__ __nv_bfloat16 Bhi[BK][BSTR];
    __shared__ __nv_bfloat16 Blo[BK][BSTR];

    const int tid  = threadIdx.x;
    const int lane = tid & 31;
    const int wid  = tid >> 5;
    const int warp_m = wid & 3;
    const int warp_n = wid >> 2;
    const int row0 = blockIdx.y * BM;
    const int col0 = blockIdx.x * BN;

    const int ar = tid >> 1;
    const int ac = (tid & 1) * 16;
    const int br = tid >> 3;
    const int bc = (tid & 7) * 16;

    float4 aReg[4], bReg[4];
    const float* aPtr = A + (size_t)(row0 + ar) * K + ac;
    const float* bPtr = W + (size_t)br * N + col0 + bc;

    #pragma unroll
    for (int i = 0; i < 4; i++) aReg[i] = *(const float4*)(aPtr + i * 4);
    #pragma unroll
    for (int i = 0; i < 4; i++) bReg[i] = *(const float4*)(bPtr + i * 4);

    float acc[2][8][4];
    #pragma unroll
    for (int mt = 0; mt < 2; mt++)
        #pragma unroll
        for (int j = 0; j < 8; j++)
            #pragma unroll
            for (int r = 0; r < 4; r++) acc[mt][j][r] = 0.f;

    const int lrow = lane & 15;
    const int lcol8 = (lane >> 4) * 8;

    const int nTiles = K / BK;
    for (int kt = 0; kt < nTiles; kt++) {
        #pragma unroll
        for (int i = 0; i < 4; i++) {
            float4 v = aReg[i];
            *(__nv_bfloat162*)(&Ahi[ar][ac + i * 4 + 0]) = split_hi(v.x, v.y);
            *(__nv_bfloat162*)(&Ahi[ar][ac + i * 4 + 2]) = split_hi(v.z, v.w);
            *(__nv_bfloat162*)(&Alo[ar][ac + i * 4 + 0]) = split_lo(v.x, v.y);
            *(__nv_bfloat162*)(&Alo[ar][ac + i * 4 + 2]) = split_lo(v.z, v.w);
        }
        #pragma unroll
        for (int i = 0; i < 4; i++) {
            float4 v = bReg[i];
            *(__nv_bfloat162*)(&Bhi[br][bc + i * 4 + 0]) = split_hi(v.x, v.y);
            *(__nv_bfloat162*)(&Bhi[br][bc + i * 4 + 2]) = split_hi(v.z, v.w);
            *(__nv_bfloat162*)(&Blo[br][bc + i * 4 + 0]) = split_lo(v.x, v.y);
            *(__nv_bfloat162*)(&Blo[br][bc + i * 4 + 2]) = split_lo(v.z, v.w);
        }
        __syncthreads();

        if (kt + 1 < nTiles) {
            const float* aN = aPtr + (kt + 1) * BK;
            const float* bN = bPtr + (size_t)(kt + 1) * BK * N;
            #pragma unroll
            for (int i = 0; i < 4; i++) aReg[i] = *(const float4*)(aN + i * 4);
            #pragma unroll
            for (int i = 0; i < 4; i++) bReg[i] = *(const float4*)(bN + i * 4);
        }

        #pragma unroll
        for (int ks = 0; ks < 2; ks++) {
            uint32_t ah[2][4], al[2][4];
            #pragma unroll
            for (int mt = 0; mt < 2; mt++) {
                int r = warp_m * 32 + mt * 16 + lrow;
                int c = ks * 16 + lcol8;
                ldsm4(ah[mt], smem_u32(&Ahi[r][c]));
                ldsm4(al[mt], smem_u32(&Alo[r][c]));
            }
            uint32_t bh[4][4], bl[4][4];
            #pragma unroll
            for (int g = 0; g < 4; g++) {
                int r = ks * 16 + lrow;
                int c = warp_n * 64 + g * 16 + lcol8;
                ldsm4t(bh[g], smem_u32(&Bhi[r][c]));
                ldsm4t(bl[g], smem_u32(&Blo[r][c]));
            }
            #pragma unroll
            for (int mt = 0; mt < 2; mt++) {
                #pragma unroll
                for (int g = 0; g < 4; g++) {
                    mma_bf16(acc[mt][2 * g],     ah[mt], &bh[g][0]);
                    mma_bf16(acc[mt][2 * g],     ah[mt], &bl[g][0]);
                    mma_bf16(acc[mt][2 * g],     al[mt], &bh[g][0]);
                    mma_bf16(acc[mt][2 * g + 1], ah[mt], &bh[g][2]);
                    mma_bf16(acc[mt][2 * g + 1], ah[mt], &bl[g][2]);
                    mma_bf16(acc[mt][2 * g + 1], al[mt], &bh[g][2]);
                }
            }
        }
        __syncthreads();
    }

    const int erow = row0 + warp_m * 32 + (lane >> 2);
    const int ecol = col0 + warp_n * 64 + (lane & 3) * 2;
    #pragma unroll
    for (int mt = 0; mt < 2; mt++) {
        #pragma unroll
        for (int j = 0; j < 8; j++) {
            int c = ecol + j * 8;
            float b0 = bias[c], b1 = bias[c + 1];
            int r = erow + mt * 16;
            float2 v0 = make_float2(acc[mt][j][0] + b0, acc[mt][j][1] + b1);
            float2 v1 = make_float2(acc[mt][j][2] + b0, acc[mt][j][3] + b1);
            *(float2*)(C + (size_t)r * N + c) = v0;
            *(float2*)(C + (size_t)(r + 8) * N + c) = v1;
        }
    }
}

// ---------------------------------------------------------------------------
// Tensor-core causal flash attention, bf16x3 emulated fp32.
// Block: 128 threads = 4 warps, each warp owns 16 query rows (BQ=64).
// K/V tiles of 64 keys staged in SMEM as bf16 hi/lo. grid=(S/64, B*H).
// ---------------------------------------------------------------------------
__global__ __launch_bounds__(128) void attn_tc_kernel(
    const float* __restrict__ Q, const float* __restrict__ K,
    const float* __restrict__ V, float* __restrict__ O)
{
    constexpr int BQ = 64, BKEY = 64, STR = 72;
    __shared__ __nv_bfloat16 Khi[BKEY][STR];
    __shared__ __nv_bfloat16 Klo[BKEY][STR];
    __shared__ __nv_bfloat16 Vhi[BKEY][STR];
    __shared__ __nv_bfloat16 Vlo[BKEY][STR];

    const int tid  = threadIdx.x;
    const int lane = tid & 31;
    const int warp = tid >> 5;
    const int bh = blockIdx.y;
    const int b = bh >> 4;
    const int h = bh & 15;
    const int q0 = blockIdx.x * BQ;

    const float* qbase = Q + ((size_t)(b * Ss + q0)) * Ee + h * Dd;
    const float* kbase = K + ((size_t)(b * Ss)) * Ee + h * Dd;
    const float* vbase = V + ((size_t)(b * Ss)) * Ee + h * Dd;

    const int lrow  = lane & 15;
    const int lcol8 = (lane >> 4) * 8;

    // ---- Stage Q tile (64x64) into Khi/Klo, then load A-fragments to regs ----
    #pragma unroll
    for (int it = 0; it < 8; it++) {
        int idx = tid + it * 128;          // 0..1023
        int r = idx >> 4;                  // 0..63
        int c = (idx & 15) * 4;            // 0..60
        float4 v = *(const float4*)(qbase + (size_t)r * Ee + c);
        *(__nv_bfloat162*)(&Khi[r][c + 0]) = split_hi(v.x, v.y);
        *(__nv_bfloat162*)(&Khi[r][c + 2]) = split_hi(v.z, v.w);
        *(__nv_bfloat162*)(&Klo[r][c + 0]) = split_lo(v.x, v.y);
        *(__nv_bfloat162*)(&Klo[r][c + 2]) = split_lo(v.z, v.w);
    }
    __syncthreads();

    uint32_t qh[4][4], ql[4][4];
    #pragma unroll
    for (int ks = 0; ks < 4; ks++) {
        int r = warp * 16 + lrow;
        int c = ks * 16 + lcol8;
        ldsm4(qh[ks], smem_u32(&Khi[r][c]));
        ldsm4(ql[ks], smem_u32(&Klo[r][c]));
    }

    float o[8][4];
    #pragma unroll
    for (int nt = 0; nt < 8; nt++)
        #pragma unroll
        for (int r = 0; r < 4; r++) o[nt][r] = 0.f;
    float m0 = -1e30f, m1 = -1e30f, l0 = 0.f, l1 = 0.f;

    const int ntiles = blockIdx.x + 1;
    for (int kt = 0; kt < ntiles; kt++) {
        __syncthreads();
        // ---- Load K,V tile kt (64 keys x 64 d), convert to hi/lo bf16 ----
        #pragma unroll
        for (int it = 0; it < 8; it++) {
            int idx = tid + it * 128;
            int r = idx >> 4;
            int c = (idx & 15) * 4;
            size_t goff = (size_t)(kt * BKEY + r) * Ee + c;
            float4 kv = *(const float4*)(kbase + goff);
            *(__nv_bfloat162*)(&Khi[r][c + 0]) = split_hi(kv.x, kv.y);
            *(__nv_bfloat162*)(&Khi[r][c + 2]) = split_hi(kv.z, kv.w);
            *(__nv_bfloat162*)(&Klo[r][c + 0]) = split_lo(kv.x, kv.y);
            *(__nv_bfloat162*)(&Klo[r][c + 2]) = split_lo(kv.z, kv.w);
            float4 vv = *(const float4*)(vbase + goff);
            *(__nv_bfloat162*)(&Vhi[r][c + 0]) = split_hi(vv.x, vv.y);
            *(__nv_bfloat162*)(&Vhi[r][c + 2]) = split_hi(vv.z, vv.w);
            *(__nv_bfloat162*)(&Vlo[r][c + 0]) = split_lo(vv.x, vv.y);
            *(__nv_bfloat162*)(&Vlo[r][c + 2]) = split_lo(vv.z, vv.w);
        }
        __syncthreads();

        // ---- S = Q @ K^T (bf16x3), m16 x n64, k=64 ----
        float s[8][4];
        #pragma unroll
        for (int nt = 0; nt < 8; nt++)
            #pragma unroll
            for (int r = 0; r < 4; r++) s[nt][r] = 0.f;

        #pragma unroll
        for (int kg = 0; kg < 4; kg++) {        // 16-key group (2 n8 tiles)
            #pragma unroll
            for (int ks = 0; ks < 4; ks++) {    // k16 step over D
                uint32_t kh[4], kl[4];
                int r = kg * 16 + lrow;
                int c = ks * 16 + lcol8;
                ldsm4(kh, smem_u32(&Khi[r][c]));
                ldsm4(kl, smem_u32(&Klo[r][c]));
                // n8 tile 2kg: keys kg*16..+7 -> b = {m0, m2}
                mma_b2(s[2 * kg],     qh[ks], kh[0], kh[2]);
                mma_b2(s[2 * kg],     qh[ks], kl[0], kl[2]);
                mma_b2(s[2 * kg],     ql[ks], kh[0], kh[2]);
                // n8 tile 2kg+1: keys kg*16+8..+15 -> b = {m1, m3}
                mma_b2(s[2 * kg + 1], qh[ks], kh[1], kh[3]);
                mma_b2(s[2 * kg + 1], qh[ks], kl[1], kl[3]);
                mma_b2(s[2 * kg + 1], ql[ks], kh[1], kh[3]);
            }
        }

        // ---- scale + causal mask (diagonal tile only) ----
        #pragma unroll
        for (int nt = 0; nt < 8; nt++)
            #pragma unroll
            for (int r = 0; r < 4; r++) s[nt][r] *= 0.125f;

        if (kt == blockIdx.x) {
            int qloc0 = warp * 16 + (lane >> 2);
            int qloc1 = qloc0 + 8;
            #pragma unroll
            for (int nt = 0; nt < 8; nt++) {
                int key0 = nt * 8 + 2 * (lane & 3);
                if (key0     > qloc0) s[nt][0] = -10000.f;
                if (key0 + 1 > qloc0) s[nt][1] = -10000.f;
                if (key0     > qloc1) s[nt][2] = -10000.f;
                if (key0 + 1 > qloc1) s[nt][3] = -10000.f;
            }
        }

        // ---- online softmax (two rows per lane) ----
        float tm0 = -1e30f, tm1 = -1e30f;
        #pragma unroll
        for (int nt = 0; nt < 8; nt++) {
            tm0 = fmaxf(tm0, fmaxf(s[nt][0], s[nt][1]));
            tm1 = fmaxf(tm1, fmaxf(s[nt][2], s[nt][3]));
        }
        tm0 = fmaxf(tm0, __shfl_xor_sync(0xffffffffu, tm0, 1));
        tm0 = fmaxf(tm0, __shfl_xor_sync(0xffffffffu, tm0, 2));
        tm1 = fmaxf(tm1, __shfl_xor_sync(0xffffffffu, tm1, 1));
        tm1 = fmaxf(tm1, __shfl_xor_sync(0xffffffffu, tm1, 2));

        float mn0 = fmaxf(m0, tm0);
        float mn1 = fmaxf(m1, tm1);
        float sc0 = __expf(m0 - mn0);
        float sc1 = __expf(m1 - mn1);
        m0 = mn0; m1 = mn1;

        float rs0 = 0.f, rs1 = 0.f;
        #pragma unroll
        for (int nt = 0; nt < 8; nt++) {
            s[nt][0] = __expf(s[nt][0] - m0);
            s[nt][1] = __expf(s[nt][1] - m0);
            s[nt][2] = __expf(s[nt][2] - m1);
            s[nt][3] = __expf(s[nt][3] - m1);
            rs0 += s[nt][0] + s[nt][1];
            rs1 += s[nt][2] + s[nt][3];
        }
        rs0 += __shfl_xor_sync(0xffffffffu, rs0, 1);
        rs0 += __shfl_xor_sync(0xffffffffu, rs0, 2);
        rs1 += __shfl_xor_sync(0xffffffffu, rs1, 1);
        rs1 += __shfl_xor_sync(0xffffffffu, rs1, 2);
        l0 = l0 * sc0 + rs0;
        l1 = l1 * sc1 + rs1;

        #pragma unroll
        for (int nt = 0; nt < 8; nt++) {
            o[nt][0] *= sc0; o[nt][1] *= sc0;
            o[nt][2] *= sc1; o[nt][3] *= sc1;
        }

        // ---- pack P into A-fragments (hi/lo) ----
        uint32_t ph[4][4], pl[4][4];
        #pragma unroll
        for (int kk = 0; kk < 4; kk++) {
            int t0 = 2 * kk, t1 = 2 * kk + 1;
            ph[kk][0] = pack_hi(s[t0][0], s[t0][1]);
            ph[kk][1] = pack_hi(s[t0][2], s[t0][3]);
            ph[kk][2] = pack_hi(s[t1][0], s[t1][1]);
            ph[kk][3] = pack_hi(s[t1][2], s[t1][3]);
            pl[kk][0] = pack_lo(s[t0][0], s[t0][1]);
            pl[kk][1] = pack_lo(s[t0][2], s[t0][3]);
            pl[kk][2] = pack_lo(s[t1][0], s[t1][1]);
            pl[kk][3] = pack_lo(s[t1][2], s[t1][3]);
        }

        // ---- O += P @ V (bf16x3), m16 x n64, k=64 ----
        #pragma unroll
        for (int kk = 0; kk < 4; kk++) {        // k16 step over keys
            #pragma unroll
            for (int g = 0; g < 4; g++) {       // 16-col d group (2 n8 tiles)
                uint32_t vh[4], vl[4];
                int r = kk * 16 + lrow;
                int c = g * 16 + lcol8;
                ldsm4t(vh, smem_u32(&Vhi[r][c]));
                ldsm4t(vl, smem_u32(&Vlo[r][c]));
                mma_b2(o[2 * g],     ph[kk], vh[0], vh[1]);
                mma_b2(o[2 * g],     ph[kk], vl[0], vl[1]);
                mma_b2(o[2 * g],     pl[kk], vh[0], vh[1]);
                mma_b2(o[2 * g + 1], ph[kk], vh[2], vh[3]);
                mma_b2(o[2 * g + 1], ph[kk], vl[2], vl[3]);
                mma_b2(o[2 * g + 1], pl[kk], vh[2], vh[3]);
            }
        }
    }

    // ---- epilogue: normalize and store ----
    const float inv0 = 1.f / l0;
    const float inv1 = 1.f / l1;
    const int row0 = q0 + warp * 16 + (lane >> 2);
    const int col0 = h * Dd + 2 * (lane & 3);
    #pragma unroll
    for (int nt = 0; nt < 8; nt++) {
        int c = col0 + nt * 8;
        *(float2*)(O + (size_t)(b * Ss + row0) * Ee + c) =
            make_float2(o[nt][0] * inv0, o[nt][1] * inv0);
        *(float2*)(O + (size_t)(b * Ss + row0 + 8) * Ee + c) =
            make_float2(o[nt][2] * inv1, o[nt][3] * inv1);
    }
}

// ---------------------------------------------------------------------------
extern "C" void kernel_launch(void* const* d_in, const int* in_sizes, int n_in,
                              void* d_out, int out_size)
{
    const float* x  = (const float*)d_in[0];
    const float* Wq = (const float*)d_in[1];
    const float* bq = (const float*)d_in[2];
    const float* Wk = (const float*)d_in[3];
    const float* bk = (const float*)d_in[4];
    const float* Wv = (const float*)d_in[5];
    const float* bv = (const float*)d_in[6];
    const float* Wo = (const float*)d_in[7];
    const float* bo = (const float*)d_in[8];
    float* out = (float*)d_out;

    float *Qb, *Kb, *Vb, *Ab;
    cudaGetSymbolAddress((void**)&Qb, g_Q);
    cudaGetSymbolAddress((void**)&Kb, g_K);
    cudaGetSymbolAddress((void**)&Vb, g_V);
    cudaGetSymbolAddress((void**)&Ab, g_A);

    dim3 gemmGrid(Ee / 128, MM / 128);   // (8, 32)
    dim3 gemmBlk(256);

    gemm_bias_tc_kernel<<<gemmGrid, gemmBlk>>>(x, Wq, bq, Qb, MM, Ee, Ee);
    gemm_bias_tc_kernel<<<gemmGrid, gemmBlk>>>(x, Wk, bk, Kb, MM, Ee, Ee);
    gemm_bias_tc_kernel<<<gemmGrid, gemmBlk>>>(x, Wv, bv, Vb, MM, Ee, Ee);

    dim3 attnGrid(Ss / 64, Bb * Hh);     // (32, 32)
    attn_tc_kernel<<<attnGrid, 128>>>(Qb, Kb, Vb, Ab);

    gemm_bias_tc_kernel<<<gemmGrid, gemmBlk>>>(Ab, Wo, bo, out, MM, Ee, Ee);
}

// round 8
// speedup vs baseline: 3.0353x; 1.1468x over previous
#include <cuda_runtime.h>
#include <cuda_bf16.h>
#include <cstdint>

// Problem constants
#define Bb 2
#define Ss 2048
#define Ee 1024
#define Hh 16
#define Dd 64
#define MM (Bb * Ss)   // 4096 rows

// ---------------------------------------------------------------------------
// Device-global scratch (no cudaMalloc allowed)
// ---------------------------------------------------------------------------
__device__ __nv_bfloat16 g_Xh[MM * Ee],  g_Xl[MM * Ee];     // split input
__device__ __nv_bfloat16 g_Wqh[Ee * Ee], g_Wql[Ee * Ee];
__device__ __nv_bfloat16 g_Wkh[Ee * Ee], g_Wkl[Ee * Ee];
__device__ __nv_bfloat16 g_Wvh[Ee * Ee], g_Wvl[Ee * Ee];
__device__ __nv_bfloat16 g_Woh[Ee * Ee], g_Wol[Ee * Ee];
// Q/K/V head-major: [B*H][S][D]
__device__ __nv_bfloat16 g_Qh[MM * Ee], g_Ql[MM * Ee];
__device__ __nv_bfloat16 g_Kh[MM * Ee], g_Kl[MM * Ee];
__device__ __nv_bfloat16 g_Vh[MM * Ee], g_Vl[MM * Ee];
// attention output, row-major [M][E]
__device__ __nv_bfloat16 g_Ah[MM * Ee], g_Al[MM * Ee];

// ---------------------------------------------------------------------------
// PTX helpers
// ---------------------------------------------------------------------------
__device__ __forceinline__ uint32_t smem_u32(const void* p) {
    return (uint32_t)__cvta_generic_to_shared(p);
}
__device__ __forceinline__ void ldsm4(uint32_t* r, uint32_t addr) {
    asm volatile("ldmatrix.sync.aligned.m8n8.x4.shared.b16 {%0,%1,%2,%3}, [%4];"
                 : "=r"(r[0]), "=r"(r[1]), "=r"(r[2]), "=r"(r[3]) : "r"(addr));
}
__device__ __forceinline__ void ldsm4t(uint32_t* r, uint32_t addr) {
    asm volatile("ldmatrix.sync.aligned.m8n8.x4.trans.shared.b16 {%0,%1,%2,%3}, [%4];"
                 : "=r"(r[0]), "=r"(r[1]), "=r"(r[2]), "=r"(r[3]) : "r"(addr));
}
__device__ __forceinline__ void mma_bf16(float* c, const uint32_t* a, const uint32_t* b) {
    asm volatile(
        "mma.sync.aligned.m16n8k16.row.col.f32.bf16.bf16.f32 "
        "{%0,%1,%2,%3}, {%4,%5,%6,%7}, {%8,%9}, {%0,%1,%2,%3};"
        : "+f"(c[0]), "+f"(c[1]), "+f"(c[2]), "+f"(c[3])
        : "r"(a[0]), "r"(a[1]), "r"(a[2]), "r"(a[3]), "r"(b[0]), "r"(b[1]));
}
__device__ __forceinline__ void mma_b2(float* c, const uint32_t* a, uint32_t b0, uint32_t b1) {
    asm volatile(
        "mma.sync.aligned.m16n8k16.row.col.f32.bf16.bf16.f32 "
        "{%0,%1,%2,%3}, {%4,%5,%6,%7}, {%8,%9}, {%0,%1,%2,%3};"
        : "+f"(c[0]), "+f"(c[1]), "+f"(c[2]), "+f"(c[3])
        : "r"(a[0]), "r"(a[1]), "r"(a[2]), "r"(a[3]), "r"(b0), "r"(b1));
}
__device__ __forceinline__ __nv_bfloat162 split_hi(float x0, float x1) {
    return __nv_bfloat162(__float2bfloat16(x0), __float2bfloat16(x1));
}
__device__ __forceinline__ __nv_bfloat162 split_lo(float x0, float x1) {
    float h0 = __bfloat162float(__float2bfloat16(x0));
    float h1 = __bfloat162float(__float2bfloat16(x1));
    return __nv_bfloat162(__float2bfloat16(x0 - h0), __float2bfloat16(x1 - h1));
}
__device__ __forceinline__ uint32_t pack_hi(float x0, float x1) {
    __nv_bfloat162 t = split_hi(x0, x1);
    return *(uint32_t*)&t;
}
__device__ __forceinline__ uint32_t pack_lo(float x0, float x1) {
    __nv_bfloat162 t = split_lo(x0, x1);
    return *(uint32_t*)&t;
}

// ---------------------------------------------------------------------------
// fp32 -> (hi, lo) bf16 split, elementwise. n multiple of 4.
// ---------------------------------------------------------------------------
__global__ __launch_bounds__(256) void split_kernel(
    const float* __restrict__ in, __nv_bfloat16* __restrict__ hi,
    __nv_bfloat16* __restrict__ lo, int n4)
{
    int i = blockIdx.x * blockDim.x + threadIdx.x;
    if (i >= n4) return;
    float4 v = ((const float4*)in)[i];
    ((__nv_bfloat162*)hi)[2 * i]     = split_hi(v.x, v.y);
    ((__nv_bfloat162*)hi)[2 * i + 1] = split_hi(v.z, v.w);
    ((__nv_bfloat162*)lo)[2 * i]     = split_lo(v.x, v.y);
    ((__nv_bfloat162*)lo)[2 * i + 1] = split_lo(v.z, v.w);
}

// ---------------------------------------------------------------------------
// Shared GEMM core: acc[2][8][4] += Ah/Al[M,K] @ Wh/Wl[K,N] (bf16x3 emulation)
// BM=128, BN=128, BK=32, 256 threads = 8 warps (4m x 2n), warp tile 32x64.
// ---------------------------------------------------------------------------
__device__ __forceinline__ void gemm_core(
    float acc[2][8][4],
    const __nv_bfloat16* __restrict__ Ahg, const __nv_bfloat16* __restrict__ Alg,
    const __nv_bfloat16* __restrict__ Whg, const __nv_bfloat16* __restrict__ Wlg,
    int row0, int col0)
{
    constexpr int BM = 128, BK = 32, ASTR = 40, BSTR = 136;
    constexpr int K = Ee, N = Ee;
    __shared__ __nv_bfloat16 Ahi[BM][ASTR];
    __shared__ __nv_bfloat16 Alo[BM][ASTR];
    __shared__ __nv_bfloat16 Bhi[BK][BSTR];
    __shared__ __nv_bfloat16 Blo[BK][BSTR];

    const int tid  = threadIdx.x;
    const int lane = tid & 31;
    const int wid  = tid >> 5;
    const int warp_m = wid & 3;
    const int warp_n = wid >> 2;

    const int ar = tid >> 1;            // 0..127
    const int ac = (tid & 1) * 16;      // 0 or 16
    const int br = tid >> 3;            // 0..31
    const int bc = (tid & 7) * 16;      // 0..112

    const __nv_bfloat16* aPtrH = Ahg + (size_t)(row0 + ar) * K + ac;
    const __nv_bfloat16* aPtrL = Alg + (size_t)(row0 + ar) * K + ac;
    const __nv_bfloat16* bPtrH = Whg + (size_t)br * N + col0 + bc;
    const __nv_bfloat16* bPtrL = Wlg + (size_t)br * N + col0 + bc;

    uint4 aH[2], aL[2], bH[2], bL[2];
    #pragma unroll
    for (int i = 0; i < 2; i++) {
        aH[i] = *(const uint4*)(aPtrH + i * 8);
        aL[i] = *(const uint4*)(aPtrL + i * 8);
        bH[i] = *(const uint4*)(bPtrH + i * 8);
        bL[i] = *(const uint4*)(bPtrL + i * 8);
    }

    const int lrow  = lane & 15;
    const int lcol8 = (lane >> 4) * 8;

    const int nTiles = K / BK;
    for (int kt = 0; kt < nTiles; kt++) {
        *(uint4*)&Ahi[ar][ac]     = aH[0];
        *(uint4*)&Ahi[ar][ac + 8] = aH[1];
        *(uint4*)&Alo[ar][ac]     = aL[0];
        *(uint4*)&Alo[ar][ac + 8] = aL[1];
        *(uint4*)&Bhi[br][bc]     = bH[0];
        *(uint4*)&Bhi[br][bc + 8] = bH[1];
        *(uint4*)&Blo[br][bc]     = bL[0];
        *(uint4*)&Blo[br][bc + 8] = bL[1];
        __syncthreads();

        if (kt + 1 < nTiles) {
            const __nv_bfloat16* aNH = aPtrH + (kt + 1) * BK;
            const __nv_bfloat16* aNL = aPtrL + (kt + 1) * BK;
            const __nv_bfloat16* bNH = bPtrH + (size_t)(kt + 1) * BK * N;
            const __nv_bfloat16* bNL = bPtrL + (size_t)(kt + 1) * BK * N;
            #pragma unroll
            for (int i = 0; i < 2; i++) {
                aH[i] = *(const uint4*)(aNH + i * 8);
                aL[i] = *(const uint4*)(aNL + i * 8);
                bH[i] = *(const uint4*)(bNH + i * 8);
                bL[i] = *(const uint4*)(bNL + i * 8);
            }
        }

        #pragma unroll
        for (int ks = 0; ks < 2; ks++) {
            uint32_t ah[2][4], al[2][4];
            #pragma unroll
            for (int mt = 0; mt < 2; mt++) {
                int r = warp_m * 32 + mt * 16 + lrow;
                int c = ks * 16 + lcol8;
                ldsm4(ah[mt], smem_u32(&Ahi[r][c]));
                ldsm4(al[mt], smem_u32(&Alo[r][c]));
            }
            uint32_t bh[4][4], bl[4][4];
            #pragma unroll
            for (int g = 0; g < 4; g++) {
                int r = ks * 16 + lrow;
                int c = warp_n * 64 + g * 16 + lcol8;
                ldsm4t(bh[g], smem_u32(&Bhi[r][c]));
                ldsm4t(bl[g], smem_u32(&Blo[r][c]));
            }
            #pragma unroll
            for (int mt = 0; mt < 2; mt++) {
                #pragma unroll
                for (int g = 0; g < 4; g++) {
                    mma_bf16(acc[mt][2 * g],     ah[mt], &bh[g][0]);
                    mma_bf16(acc[mt][2 * g],     ah[mt], &bl[g][0]);
                    mma_bf16(acc[mt][2 * g],     al[mt], &bh[g][0]);
                    mma_bf16(acc[mt][2 * g + 1], ah[mt], &bh[g][2]);
                    mma_bf16(acc[mt][2 * g + 1], ah[mt], &bl[g][2]);
                    mma_bf16(acc[mt][2 * g + 1], al[mt], &bh[g][2]);
                }
            }
        }
        __syncthreads();
    }
}

// ---------------------------------------------------------------------------
// QKV projection: z selects {Wq->Q, Wk->K, Wv->V}. Output hi/lo bf16,
// head-major [B*H][S][D]. grid=(8, 32, 3), block 256.
// ---------------------------------------------------------------------------
__global__ __launch_bounds__(256) void gemm_qkv_kernel(
    const float* __restrict__ bq, const float* __restrict__ bk,
    const float* __restrict__ bv)
{
    const __nv_bfloat16 *Wh, *Wl;
    __nv_bfloat16 *Dh, *Dl;
    const float* bias;
    if (blockIdx.z == 0)      { Wh = g_Wqh; Wl = g_Wql; Dh = g_Qh; Dl = g_Ql; bias = bq; }
    else if (blockIdx.z == 1) { Wh = g_Wkh; Wl = g_Wkl; Dh = g_Kh; Dl = g_Kl; bias = bk; }
    else                      { Wh = g_Wvh; Wl = g_Wvl; Dh = g_Vh; Dl = g_Vl; bias = bv; }

    const int row0 = blockIdx.y * 128;
    const int col0 = blockIdx.x * 128;

    float acc[2][8][4];
    #pragma unroll
    for (int mt = 0; mt < 2; mt++)
        #pragma unroll
        for (int j = 0; j < 8; j++)
            #pragma unroll
            for (int r = 0; r < 4; r++) acc[mt][j][r] = 0.f;

    gemm_core(acc, g_Xh, g_Xl, Wh, Wl, row0, col0);

    const int lane = threadIdx.x & 31;
    const int wid  = threadIdx.x >> 5;
    const int erow = row0 + (wid & 3) * 32 + (lane >> 2);
    const int ecol = col0 + (wid >> 2) * 64 + (lane & 3) * 2;
    const int b = erow >> 11;             // /Ss
    const int s = erow & (Ss - 1);
    #pragma unroll
    for (int mt = 0; mt < 2; mt++) {
        #pragma unroll
        for (int j = 0; j < 8; j++) {
            int c = ecol + j * 8;
            int h = c >> 6, d = c & 63;
            float b0 = bias[c], b1 = bias[c + 1];
            float x0 = acc[mt][j][0] + b0, x1 = acc[mt][j][1] + b1;
            float y0 = acc[mt][j][2] + b0, y1 = acc[mt][j][3] + b1;
            int s0 = s + mt * 16;
            size_t d0 = ((size_t)(b * Hh + h) * Ss + s0) * Dd + d;
            size_t d1 = d0 + 8 * Dd;      // row s0+8
            *(__nv_bfloat162*)&Dh[d0] = split_hi(x0, x1);
            *(__nv_bfloat162*)&Dl[d0] = split_lo(x0, x1);
            *(__nv_bfloat162*)&Dh[d1] = split_hi(y0, y1);
            *(__nv_bfloat162*)&Dl[d1] = split_lo(y0, y1);
        }
    }
}

// ---------------------------------------------------------------------------
// Output projection: out = A @ Wo + bo, fp32 output. grid=(8, 32), block 256.
// ---------------------------------------------------------------------------
__global__ __launch_bounds__(256) void gemm_out_kernel(
    const float* __restrict__ bias, float* __restrict__ C)
{
    const int row0 = blockIdx.y * 128;
    const int col0 = blockIdx.x * 128;

    float acc[2][8][4];
    #pragma unroll
    for (int mt = 0; mt < 2; mt++)
        #pragma unroll
        for (int j = 0; j < 8; j++)
            #pragma unroll
            for (int r = 0; r < 4; r++) acc[mt][j][r] = 0.f;

    gemm_core(acc, g_Ah, g_Al, g_Woh, g_Wol, row0, col0);

    const int lane = threadIdx.x & 31;
    const int wid  = threadIdx.x >> 5;
    const int erow = row0 + (wid & 3) * 32 + (lane >> 2);
    const int ecol = col0 + (wid >> 2) * 64 + (lane & 3) * 2;
    #pragma unroll
    for (int mt = 0; mt < 2; mt++) {
        #pragma unroll
        for (int j = 0; j < 8; j++) {
            int c = ecol + j * 8;
            float b0 = bias[c], b1 = bias[c + 1];
            int r = erow + mt * 16;
            *(float2*)(C + (size_t)r * Ee + c) =
                make_float2(acc[mt][j][0] + b0, acc[mt][j][1] + b1);
            *(float2*)(C + (size_t)(r + 8) * Ee + c) =
                make_float2(acc[mt][j][2] + b0, acc[mt][j][3] + b1);
        }
    }
}

// ---------------------------------------------------------------------------
// Tensor-core causal flash attention, bf16x3, pre-split hi/lo inputs.
// Block: 128 threads = 4 warps x 16 query rows (BQ=64). grid=(S/64, B*H).
// Reads g_Q/K/V (head-major), writes g_Ah/g_Al (row-major [M][E]).
// ---------------------------------------------------------------------------
__global__ __launch_bounds__(128) void attn_tc_kernel()
{
    constexpr int BQ = 64, BKEY = 64, STR = 72;
    __shared__ __nv_bfloat16 Khi[BKEY][STR];
    __shared__ __nv_bfloat16 Klo[BKEY][STR];
    __shared__ __nv_bfloat16 Vhi[BKEY][STR];
    __shared__ __nv_bfloat16 Vlo[BKEY][STR];

    const int tid  = threadIdx.x;
    const int lane = tid & 31;
    const int warp = tid >> 5;
    const int bh = blockIdx.y;            // b*H + h (head-major index)
    const int q0 = blockIdx.x * BQ;

    const size_t hbase = (size_t)bh * Ss * Dd;
    const __nv_bfloat16* qhB = g_Qh + hbase;
    const __nv_bfloat16* qlB = g_Ql + hbase;
    const __nv_bfloat16* khB = g_Kh + hbase;
    const __nv_bfloat16* klB = g_Kl + hbase;
    const __nv_bfloat16* vhB = g_Vh + hbase;
    const __nv_bfloat16* vlB = g_Vl + hbase;

    const int lrow  = lane & 15;
    const int lcol8 = (lane >> 4) * 8;

    // ---- Stage Q tile (64x64) into Khi/Klo, load A-fragments ----
    #pragma unroll
    for (int it = 0; it < 4; it++) {
        int idx = tid + it * 128;          // 0..511
        int r = idx >> 3;                  // 0..63
        int ch = (idx & 7) * 8;            // 0..56
        size_t g = (size_t)(q0 + r) * Dd + ch;
        *(uint4*)&Khi[r][ch] = *(const uint4*)(qhB + g);
        *(uint4*)&Klo[r][ch] = *(const uint4*)(qlB + g);
    }
    __syncthreads();

    uint32_t qh[4][4], ql[4][4];
    #pragma unroll
    for (int ks = 0; ks < 4; ks++) {
        int r = warp * 16 + lrow;
        int c = ks * 16 + lcol8;
        ldsm4(qh[ks], smem_u32(&Khi[r][c]));
        ldsm4(ql[ks], smem_u32(&Klo[r][c]));
    }

    float o[8][4];
    #pragma unroll
    for (int nt = 0; nt < 8; nt++)
        #pragma unroll
        for (int r = 0; r < 4; r++) o[nt][r] = 0.f;
    float m0 = -1e30f, m1 = -1e30f, l0 = 0.f, l1 = 0.f;

    const int ntiles = blockIdx.x + 1;
    for (int kt = 0; kt < ntiles; kt++) {
        __syncthreads();
        // ---- Copy K,V tile (bf16 hi/lo, no conversion) ----
        #pragma unroll
        for (int it = 0; it < 4; it++) {
            int idx = tid + it * 128;
            int r = idx >> 3;
            int ch = (idx & 7) * 8;
            size_t g = (size_t)(kt * BKEY + r) * Dd + ch;
            *(uint4*)&Khi[r][ch] = *(const uint4*)(khB + g);
            *(uint4*)&Klo[r][ch] = *(const uint4*)(klB + g);
            *(uint4*)&Vhi[r][ch] = *(const uint4*)(vhB + g);
            *(uint4*)&Vlo[r][ch] = *(const uint4*)(vlB + g);
        }
        __syncthreads();

        // ---- S = Q @ K^T (bf16x3) ----
        float s[8][4];
        #pragma unroll
        for (int nt = 0; nt < 8; nt++)
            #pragma unroll
            for (int r = 0; r < 4; r++) s[nt][r] = 0.f;

        #pragma unroll
        for (int kg = 0; kg < 4; kg++) {
            #pragma unroll
            for (int ks = 0; ks < 4; ks++) {
                uint32_t kh[4], kl[4];
                int r = kg * 16 + lrow;
                int c = ks * 16 + lcol8;
                ldsm4(kh, smem_u32(&Khi[r][c]));
                ldsm4(kl, smem_u32(&Klo[r][c]));
                mma_b2(s[2 * kg],     qh[ks], kh[0], kh[2]);
                mma_b2(s[2 * kg],     qh[ks], kl[0], kl[2]);
                mma_b2(s[2 * kg],     ql[ks], kh[0], kh[2]);
                mma_b2(s[2 * kg + 1], qh[ks], kh[1], kh[3]);
                mma_b2(s[2 * kg + 1], qh[ks], kl[1], kl[3]);
                mma_b2(s[2 * kg + 1], ql[ks], kh[1], kh[3]);
            }
        }

        #pragma unroll
        for (int nt = 0; nt < 8; nt++)
            #pragma unroll
            for (int r = 0; r < 4; r++) s[nt][r] *= 0.125f;

        if (kt == blockIdx.x) {
            int qloc0 = warp * 16 + (lane >> 2);
            int qloc1 = qloc0 + 8;
            #pragma unroll
            for (int nt = 0; nt < 8; nt++) {
                int key0 = nt * 8 + 2 * (lane & 3);
                if (key0     > qloc0) s[nt][0] = -10000.f;
                if (key0 + 1 > qloc0) s[nt][1] = -10000.f;
                if (key0     > qloc1) s[nt][2] = -10000.f;
                if (key0 + 1 > qloc1) s[nt][3] = -10000.f;
            }
        }

        // ---- online softmax ----
        float tm0 = -1e30f, tm1 = -1e30f;
        #pragma unroll
        for (int nt = 0; nt < 8; nt++) {
            tm0 = fmaxf(tm0, fmaxf(s[nt][0], s[nt][1]));
            tm1 = fmaxf(tm1, fmaxf(s[nt][2], s[nt][3]));
        }
        tm0 = fmaxf(tm0, __shfl_xor_sync(0xffffffffu, tm0, 1));
        tm0 = fmaxf(tm0, __shfl_xor_sync(0xffffffffu, tm0, 2));
        tm1 = fmaxf(tm1, __shfl_xor_sync(0xffffffffu, tm1, 1));
        tm1 = fmaxf(tm1, __shfl_xor_sync(0xffffffffu, tm1, 2));

        float mn0 = fmaxf(m0, tm0);
        float mn1 = fmaxf(m1, tm1);
        float sc0 = __expf(m0 - mn0);
        float sc1 = __expf(m1 - mn1);
        m0 = mn0; m1 = mn1;

        float rs0 = 0.f, rs1 = 0.f;
        #pragma unroll
        for (int nt = 0; nt < 8; nt++) {
            s[nt][0] = __expf(s[nt][0] - m0);
            s[nt][1] = __expf(s[nt][1] - m0);
            s[nt][2] = __expf(s[nt][2] - m1);
            s[nt][3] = __expf(s[nt][3] - m1);
            rs0 += s[nt][0] + s[nt][1];
            rs1 += s[nt][2] + s[nt][3];
        }
        rs0 += __shfl_xor_sync(0xffffffffu, rs0, 1);
        rs0 += __shfl_xor_sync(0xffffffffu, rs0, 2);
        rs1 += __shfl_xor_sync(0xffffffffu, rs1, 1);
        rs1 += __shfl_xor_sync(0xffffffffu, rs1, 2);
        l0 = l0 * sc0 + rs0;
        l1 = l1 * sc1 + rs1;

        #pragma unroll
        for (int nt = 0; nt < 8; nt++) {
            o[nt][0] *= sc0; o[nt][1] *= sc0;
            o[nt][2] *= sc1; o[nt][3] *= sc1;
        }

        // ---- pack P into A-fragments (hi/lo) ----
        uint32_t ph[4][4], pl[4][4];
        #pragma unroll
        for (int kk = 0; kk < 4; kk++) {
            int t0 = 2 * kk, t1 = 2 * kk + 1;
            ph[kk][0] = pack_hi(s[t0][0], s[t0][1]);
            ph[kk][1] = pack_hi(s[t0][2], s[t0][3]);
            ph[kk][2] = pack_hi(s[t1][0], s[t1][1]);
            ph[kk][3] = pack_hi(s[t1][2], s[t1][3]);
            pl[kk][0] = pack_lo(s[t0][0], s[t0][1]);
            pl[kk][1] = pack_lo(s[t0][2], s[t0][3]);
            pl[kk][2] = pack_lo(s[t1][0], s[t1][1]);
            pl[kk][3] = pack_lo(s[t1][2], s[t1][3]);
        }

        // ---- O += P @ V (bf16x3) ----
        #pragma unroll
        for (int kk = 0; kk < 4; kk++) {
            #pragma unroll
            for (int g = 0; g < 4; g++) {
                uint32_t vh[4], vl[4];
                int r = kk * 16 + lrow;
                int c = g * 16 + lcol8;
                ldsm4t(vh, smem_u32(&Vhi[r][c]));
                ldsm4t(vl, smem_u32(&Vlo[r][c]));
                mma_b2(o[2 * g],     ph[kk], vh[0], vh[1]);
                mma_b2(o[2 * g],     ph[kk], vl[0], vl[1]);
                mma_b2(o[2 * g],     pl[kk], vh[0], vh[1]);
                mma_b2(o[2 * g + 1], ph[kk], vh[2], vh[3]);
                mma_b2(o[2 * g + 1], ph[kk], vl[2], vl[3]);
                mma_b2(o[2 * g + 1], pl[kk], vh[2], vh[3]);
            }
        }
    }

    // ---- epilogue: normalize, split hi/lo, store row-major [M][E] ----
    const float inv0 = 1.f / l0;
    const float inv1 = 1.f / l1;
    const int b = bh >> 4;
    const int h = bh & 15;
    const int row0 = b * Ss + q0 + warp * 16 + (lane >> 2);
    const int col0 = h * Dd + 2 * (lane & 3);
    #pragma unroll
    for (int nt = 0; nt < 8; nt++) {
        int c = col0 + nt * 8;
        float x0 = o[nt][0] * inv0, x1 = o[nt][1] * inv0;
        float y0 = o[nt][2] * inv1, y1 = o[nt][3] * inv1;
        size_t d0 = (size_t)row0 * Ee + c;
        size_t d1 = (size_t)(row0 + 8) * Ee + c;
        *(__nv_bfloat162*)&g_Ah[d0] = split_hi(x0, x1);
        *(__nv_bfloat162*)&g_Al[d0] = split_lo(x0, x1);
        *(__nv_bfloat162*)&g_Ah[d1] = split_hi(y0, y1);
        *(__nv_bfloat162*)&g_Al[d1] = split_lo(y0, y1);
    }
}

// ---------------------------------------------------------------------------
extern "C" void kernel_launch(void* const* d_in, const int* in_sizes, int n_in,
                              void* d_out, int out_size)
{
    const float* x  = (const float*)d_in[0];
    const float* Wq = (const float*)d_in[1];
    const float* bq = (const float*)d_in[2];
    const float* Wk = (const float*)d_in[3];
    const float* bk = (const float*)d_in[4];
    const float* Wv = (const float*)d_in[5];
    const float* bv = (const float*)d_in[6];
    const float* Wo = (const float*)d_in[7];
    const float* bo = (const float*)d_in[8];
    float* out = (float*)d_out;

    __nv_bfloat16 *Xh, *Xl, *Wqh, *Wql, *Wkh, *Wkl, *Wvh, *Wvl, *Woh, *Wol;
    cudaGetSymbolAddress((void**)&Xh,  g_Xh);
    cudaGetSymbolAddress((void**)&Xl,  g_Xl);
    cudaGetSymbolAddress((void**)&Wqh, g_Wqh);
    cudaGetSymbolAddress((void**)&Wql, g_Wql);
    cudaGetSymbolAddress((void**)&Wkh, g_Wkh);
    cudaGetSymbolAddress((void**)&Wkl, g_Wkl);
    cudaGetSymbolAddress((void**)&Wvh, g_Wvh);
    cudaGetSymbolAddress((void**)&Wvl, g_Wvl);
    cudaGetSymbolAddress((void**)&Woh, g_Woh);
    cudaGetSymbolAddress((void**)&Wol, g_Wol);

    const int nX4 = MM * Ee / 4;       // 1,048,576
    const int nW4 = Ee * Ee / 4;       // 262,144
    split_kernel<<<(nX4 + 255) / 256, 256>>>(x,  Xh,  Xl,  nX4);
    split_kernel<<<(nW4 + 255) / 256, 256>>>(Wq, Wqh, Wql, nW4);
    split_kernel<<<(nW4 + 255) / 256, 256>>>(Wk, Wkh, Wkl, nW4);
    split_kernel<<<(nW4 + 255) / 256, 256>>>(Wv, Wvh, Wvl, nW4);
    split_kernel<<<(nW4 + 255) / 256, 256>>>(Wo, Woh, Wol, nW4);

    dim3 qkvGrid(Ee / 128, MM / 128, 3);     // (8, 32, 3)
    gemm_qkv_kernel<<<qkvGrid, 256>>>(bq, bk, bv);

    dim3 attnGrid(Ss / 64, Bb * Hh);         // (32, 32)
    attn_tc_kernel<<<attnGrid, 128>>>();

    dim3 outGrid(Ee / 128, MM / 128);        // (8, 32)
    gemm_out_kernel<<<outGrid, 256>>>(bo, out);
}

// round 10
// speedup vs baseline: 3.5478x; 1.1689x over previous
#include <cuda_runtime.h>
#include <cuda_bf16.h>
#include <cstdint>

// Problem constants
#define Bb 2
#define Ss 2048
#define Ee 1024
#define Hh 16
#define Dd 64
#define MM (Bb * Ss)   // 4096 rows

// ---------------------------------------------------------------------------
// Device-global scratch (no cudaMalloc allowed)
// ---------------------------------------------------------------------------
__device__ __align__(128) __nv_bfloat16 g_Xh[MM * Ee],  g_Xl[MM * Ee];   // X split, [M][K]
// Weights split AND TRANSPOSED: [N][K]
__device__ __align__(128) __nv_bfloat16 g_Wqh[Ee * Ee], g_Wql[Ee * Ee];
__device__ __align__(128) __nv_bfloat16 g_Wkh[Ee * Ee], g_Wkl[Ee * Ee];
__device__ __align__(128) __nv_bfloat16 g_Wvh[Ee * Ee], g_Wvl[Ee * Ee];
__device__ __align__(128) __nv_bfloat16 g_Woh[Ee * Ee], g_Wol[Ee * Ee];
// Q/K/V head-major: [B*H][S][D]
__device__ __align__(128) __nv_bfloat16 g_Qh[MM * Ee], g_Ql[MM * Ee];
__device__ __align__(128) __nv_bfloat16 g_Kh[MM * Ee], g_Kl[MM * Ee];
__device__ __align__(128) __nv_bfloat16 g_Vh[MM * Ee], g_Vl[MM * Ee];
// attention output, row-major [M][E]
__device__ __align__(128) __nv_bfloat16 g_Ah[MM * Ee], g_Al[MM * Ee];

// ---------------------------------------------------------------------------
// Helpers
// ---------------------------------------------------------------------------
__device__ __forceinline__ uint32_t smem_u32(const void* p) {
    return (uint32_t)__cvta_generic_to_shared(p);
}
__device__ __forceinline__ void ldsm4(uint32_t* r, uint32_t addr) {
    asm volatile("ldmatrix.sync.aligned.m8n8.x4.shared.b16 {%0,%1,%2,%3}, [%4];"
                 : "=r"(r[0]), "=r"(r[1]), "=r"(r[2]), "=r"(r[3]) : "r"(addr));
}
__device__ __forceinline__ void ldsm4t(uint32_t* r, uint32_t addr) {
    asm volatile("ldmatrix.sync.aligned.m8n8.x4.trans.shared.b16 {%0,%1,%2,%3}, [%4];"
                 : "=r"(r[0]), "=r"(r[1]), "=r"(r[2]), "=r"(r[3]) : "r"(addr));
}
__device__ __forceinline__ void mma_b2(float* c, const uint32_t* a, uint32_t b0, uint32_t b1) {
    asm volatile(
        "mma.sync.aligned.m16n8k16.row.col.f32.bf16.bf16.f32 "
        "{%0,%1,%2,%3}, {%4,%5,%6,%7}, {%8,%9}, {%0,%1,%2,%3};"
        : "+f"(c[0]), "+f"(c[1]), "+f"(c[2]), "+f"(c[3])
        : "r"(a[0]), "r"(a[1]), "r"(a[2]), "r"(a[3]), "r"(b0), "r"(b1));
}
__device__ __forceinline__ __nv_bfloat162 split_hi(float x0, float x1) {
    return __nv_bfloat162(__float2bfloat16(x0), __float2bfloat16(x1));
}
__device__ __forceinline__ __nv_bfloat162 split_lo(float x0, float x1) {
    float h0 = __bfloat162float(__float2bfloat16(x0));
    float h1 = __bfloat162float(__float2bfloat16(x1));
    return __nv_bfloat162(__float2bfloat16(x0 - h0), __float2bfloat16(x1 - h1));
}
__device__ __forceinline__ uint32_t pack_hi(float x0, float x1) {
    __nv_bfloat162 t = split_hi(x0, x1);
    return *(uint32_t*)&t;
}
__device__ __forceinline__ uint32_t pack_lo(float x0, float x1) {
    __nv_bfloat162 t = split_lo(x0, x1);
    return *(uint32_t*)&t;
}

// cp.async 16B helpers
__device__ __forceinline__ void cp16(uint32_t dst, const void* src) {
    asm volatile("cp.async.cg.shared.global [%0], [%1], 16;"
                 :: "r"(dst), "l"(src) : "memory");
}
__device__ __forceinline__ void cp_commit() {
    asm volatile("cp.async.commit_group;" ::: "memory");
}
__device__ __forceinline__ void cp_wait1() {
    asm volatile("cp.async.wait_group 1;" ::: "memory");
}

// XOR swizzle for 128B-row tiles: conflict-free ldmatrix + 16B-aligned chunks
__device__ __forceinline__ uint32_t swz(int r, int cb) {
    return (uint32_t)(r * 128 + (cb ^ ((r & 7) << 4)));
}

// ---------------------------------------------------------------------------
// fp32 -> (hi, lo) bf16 split, elementwise (for X). n multiple of 4.
// ---------------------------------------------------------------------------
__global__ __launch_bounds__(256) void split_kernel(
    const float* __restrict__ in, __nv_bfloat16* __restrict__ hi,
    __nv_bfloat16* __restrict__ lo, int n4)
{
    int i = blockIdx.x * blockDim.x + threadIdx.x;
    if (i >= n4) return;
    float4 v = ((const float4*)in)[i];
    ((__nv_bfloat162*)hi)[2 * i]     = split_hi(v.x, v.y);
    ((__nv_bfloat162*)hi)[2 * i + 1] = split_hi(v.z, v.w);
    ((__nv_bfloat162*)lo)[2 * i]     = split_lo(v.x, v.y);
    ((__nv_bfloat162*)lo)[2 * i + 1] = split_lo(v.z, v.w);
}

// ---------------------------------------------------------------------------
// Weight transpose + split: Wt[n][k] = W[k][n], hi/lo bf16.
// grid (32, 32, 4), block (32, 8).
// ---------------------------------------------------------------------------
__global__ __launch_bounds__(256) void transpose_split_kernel(
    const float* __restrict__ W0, const float* __restrict__ W1,
    const float* __restrict__ W2, const float* __restrict__ W3)
{
    const float* W;
    __nv_bfloat16 *Th, *Tl;
    switch (blockIdx.z) {
        case 0:  W = W0; Th = g_Wqh; Tl = g_Wql; break;
        case 1:  W = W1; Th = g_Wkh; Tl = g_Wkl; break;
        case 2:  W = W2; Th = g_Wvh; Tl = g_Wvl; break;
        default: W = W3; Th = g_Woh; Tl = g_Wol; break;
    }
    __shared__ float t[32][33];
    const int n0 = blockIdx.x * 32;
    const int k0 = blockIdx.y * 32;
    const int tx = threadIdx.x, ty = threadIdx.y;
    #pragma unroll
    for (int i = 0; i < 4; i++) {
        int r = ty + i * 8;
        t[r][tx] = W[(size_t)(k0 + r) * Ee + n0 + tx];
    }
    __syncthreads();
    #pragma unroll
    for (int i = 0; i < 4; i++) {
        int r = ty + i * 8;                 // n index
        float v = t[tx][r];                 // = W[k0+tx][n0+r]
        float h = __bfloat162float(__float2bfloat16(v));
        size_t dst = (size_t)(n0 + r) * Ee + k0 + tx;
        Th[dst] = __float2bfloat16(v);
        Tl[dst] = __float2bfloat16(v - h);
    }
}

// ---------------------------------------------------------------------------
// Pipelined HMMA GEMM core. Tile 128x64, BK=64, 2-stage cp.async.
// A: [M][K] hi/lo bf16.  B: [N][K] hi/lo bf16 (transposed weights).
// 256 threads = 8 warps (4m x 2n), warp tile 32x32. acc[2][4][4].
// SMEM stage (48KB): Ah@0, Al@16384, Bh@32768, Bl@40960. 2 stages = 96KB.
// ---------------------------------------------------------------------------
#define GP_STAGE 49152
#define GP_SMEM  (2 * GP_STAGE)
#define GP_NT    16

__device__ __forceinline__ void gemm_issue(
    uint32_t stg,
    const __nv_bfloat16* __restrict__ Ah, const __nv_bfloat16* __restrict__ Al,
    const __nv_bfloat16* __restrict__ Bh, const __nv_bfloat16* __restrict__ Bl,
    int row0, int col0, int kt, int tid)
{
    const int k0 = kt * 64;
    #pragma unroll
    for (int it = 0; it < 4; it++) {            // A: 128 rows x 128B, hi+lo
        int idx = tid + it * 256;               // 0..1023
        int r = idx >> 3, cq = idx & 7;
        size_t g = (size_t)(row0 + r) * Ee + k0 + cq * 8;
        uint32_t d = swz(r, cq * 16);
        cp16(stg + d,         Ah + g);
        cp16(stg + 16384 + d, Al + g);
    }
    #pragma unroll
    for (int it = 0; it < 2; it++) {            // B: 64 rows x 128B, hi+lo
        int idx = tid + it * 256;               // 0..511
        int r = idx >> 3, cq = idx & 7;
        size_t g = (size_t)(col0 + r) * Ee + k0 + cq * 8;
        uint32_t d = swz(r, cq * 16);
        cp16(stg + 32768 + d, Bh + g);
        cp16(stg + 40960 + d, Bl + g);
    }
    cp_commit();
}

__device__ __forceinline__ void gemm_pipeline(
    uint32_t sb,
    float acc[2][4][4],
    const __nv_bfloat16* __restrict__ Ah, const __nv_bfloat16* __restrict__ Al,
    const __nv_bfloat16* __restrict__ Bh, const __nv_bfloat16* __restrict__ Bl,
    int row0, int col0)
{
    const int tid  = threadIdx.x;
    const int lane = tid & 31;
    const int wid  = tid >> 5;
    const int warp_m = wid & 3;
    const int warp_n = wid >> 2;
    const int lrow  = lane & 15;
    const int lcb   = ((lane >> 4) * 8) * 2;    // 0 or 16 bytes

    gemm_issue(sb,            Ah, Al, Bh, Bl, row0, col0, 0, tid);
    gemm_issue(sb + GP_STAGE, Ah, Al, Bh, Bl, row0, col0, 1, tid);

    for (int kt = 0; kt < GP_NT; kt++) {
        const uint32_t stg = sb + (kt & 1) * GP_STAGE;
        cp_wait1();
        __syncthreads();

        #pragma unroll
        for (int ks = 0; ks < 4; ks++) {
            uint32_t ah[2][4], al[2][4];
            #pragma unroll
            for (int mt = 0; mt < 2; mt++) {
                uint32_t off = swz(warp_m * 32 + mt * 16 + lrow, ks * 32 + lcb);
                ldsm4(ah[mt], stg + off);
                ldsm4(al[mt], stg + 16384 + off);
            }
            uint32_t bh[2][4], bl[2][4];
            #pragma unroll
            for (int ng = 0; ng < 2; ng++) {
                uint32_t off = swz(warp_n * 32 + ng * 16 + lrow, ks * 32 + lcb);
                ldsm4(bh[ng], stg + 32768 + off);
                ldsm4(bl[ng], stg + 40960 + off);
            }
            #pragma unroll
            for (int mt = 0; mt < 2; mt++) {
                #pragma unroll
                for (int ng = 0; ng < 2; ng++) {
                    mma_b2(acc[mt][2 * ng],     ah[mt], bh[ng][0], bh[ng][2]);
                    mma_b2(acc[mt][2 * ng],     ah[mt], bl[ng][0], bl[ng][2]);
                    mma_b2(acc[mt][2 * ng],     al[mt], bh[ng][0], bh[ng][2]);
                    mma_b2(acc[mt][2 * ng + 1], ah[mt], bh[ng][1], bh[ng][3]);
                    mma_b2(acc[mt][2 * ng + 1], ah[mt], bl[ng][1], bl[ng][3]);
                    mma_b2(acc[mt][2 * ng + 1], al[mt], bh[ng][1], bh[ng][3]);
                }
            }
        }
        __syncthreads();
        if (kt + 2 < GP_NT)
            gemm_issue(stg, Ah, Al, Bh, Bl, row0, col0, kt + 2, tid);
        else
            cp_commit();
    }
}

// ---------------------------------------------------------------------------
// QKV projection: z selects {Wq->Q, Wk->K, Wv->V}. Output hi/lo bf16,
// head-major [B*H][S][D]. grid=(16, 32, 3), block 256. BN=64 == one head.
// ---------------------------------------------------------------------------
__global__ __launch_bounds__(256, 2)
void gemm_qkv_kernel(const float* __restrict__ bq, const float* __restrict__ bk,
                     const float* __restrict__ bv)
{
    extern __shared__ char smem[];
    const __nv_bfloat16 *Wh, *Wl;
    __nv_bfloat16 *Dh, *Dl;
    const float* bias;
    if (blockIdx.z == 0)      { Wh = g_Wqh; Wl = g_Wql; Dh = g_Qh; Dl = g_Ql; bias = bq; }
    else if (blockIdx.z == 1) { Wh = g_Wkh; Wl = g_Wkl; Dh = g_Kh; Dl = g_Kl; bias = bk; }
    else                      { Wh = g_Wvh; Wl = g_Wvl; Dh = g_Vh; Dl = g_Vl; bias = bv; }

    const int row0 = blockIdx.y * 128;
    const int col0 = blockIdx.x * 64;

    float acc[2][4][4];
    #pragma unroll
    for (int mt = 0; mt < 2; mt++)
        #pragma unroll
        for (int j = 0; j < 4; j++)
            #pragma unroll
            for (int r = 0; r < 4; r++) acc[mt][j][r] = 0.f;

    gemm_pipeline(smem_u32(smem), acc, g_Xh, g_Xl, Wh, Wl, row0, col0);

    const int lane = threadIdx.x & 31;
    const int wid  = threadIdx.x >> 5;
    const int warp_m = wid & 3, warp_n = wid >> 2;
    const int h = col0 >> 6;                      // BN=64 -> single head
    #pragma unroll
    for (int mt = 0; mt < 2; mt++) {
        int erow = row0 + warp_m * 32 + mt * 16 + (lane >> 2);
        int b = erow >> 11, sI = erow & (Ss - 1);
        #pragma unroll
        for (int nt = 0; nt < 4; nt++) {
            int gc = col0 + warp_n * 32 + nt * 8 + (lane & 3) * 2;
            int d = gc & 63;
            float b0 = bias[gc], b1 = bias[gc + 1];
            float x0 = acc[mt][nt][0] + b0, x1 = acc[mt][nt][1] + b1;
            float y0 = acc[mt][nt][2] + b0, y1 = acc[mt][nt][3] + b1;
            size_t d0 = ((size_t)((b << 4) + h) * Ss + sI) * Dd + d;
            size_t d1 = d0 + 8 * Dd;
            *(__nv_bfloat162*)&Dh[d0] = split_hi(x0, x1);
            *(__nv_bfloat162*)&Dl[d0] = split_lo(x0, x1);
            *(__nv_bfloat162*)&Dh[d1] = split_hi(y0, y1);
            *(__nv_bfloat162*)&Dl[d1] = split_lo(y0, y1);
        }
    }
}

// ---------------------------------------------------------------------------
// Output projection: out = A @ Wo + bo (fp32). grid=(16, 32), block 256.
// ---------------------------------------------------------------------------
__global__ __launch_bounds__(256, 2)
void gemm_out_kernel(const float* __restrict__ bias, float* __restrict__ C)
{
    extern __shared__ char smem[];
    const int row0 = blockIdx.y * 128;
    const int col0 = blockIdx.x * 64;

    float acc[2][4][4];
    #pragma unroll
    for (int mt = 0; mt < 2; mt++)
        #pragma unroll
        for (int j = 0; j < 4; j++)
            #pragma unroll
            for (int r = 0; r < 4; r++) acc[mt][j][r] = 0.f;

    gemm_pipeline(smem_u32(smem), acc, g_Ah, g_Al, g_Woh, g_Wol, row0, col0);

    const int lane = threadIdx.x & 31;
    const int wid  = threadIdx.x >> 5;
    const int warp_m = wid & 3, warp_n = wid >> 2;
    #pragma unroll
    for (int mt = 0; mt < 2; mt++) {
        int erow = row0 + warp_m * 32 + mt * 16 + (lane >> 2);
        #pragma unroll
        for (int nt = 0; nt < 4; nt++) {
            int gc = col0 + warp_n * 32 + nt * 8 + (lane & 3) * 2;
            float b0 = bias[gc], b1 = bias[gc + 1];
            *(float2*)(C + (size_t)erow * Ee + gc) =
                make_float2(acc[mt][nt][0] + b0, acc[mt][nt][1] + b1);
            *(float2*)(C + (size_t)(erow + 8) * Ee + gc) =
                make_float2(acc[mt][nt][2] + b0, acc[mt][nt][3] + b1);
        }
    }
}

// ---------------------------------------------------------------------------
// Tensor-core causal flash attention, bf16x3, 2-stage cp.async K/V pipeline.
// Block 128 threads = 4 warps x 16 q-rows (BQ=64). grid=(S/64, B*H).
// SMEM stage (32KB): Kh@0, Kl@8192, Vh@16384, Vl@24576. 2 stages = 64KB.
// ---------------------------------------------------------------------------
#define AT_STAGE 32768
#define AT_SMEM  (2 * AT_STAGE)

__device__ __forceinline__ void attn_issue(
    uint32_t stg,
    const __nv_bfloat16* khB, const __nv_bfloat16* klB,
    const __nv_bfloat16* vhB, const __nv_bfloat16* vlB,
    int kt, int tid)
{
    #pragma unroll
    for (int it = 0; it < 4; it++) {
        int idx = tid + it * 128;               // 0..511
        int r = idx >> 3, cq = idx & 7;
        size_t g = (size_t)(kt * 64 + r) * Dd + cq * 8;
        uint32_t d = swz(r, cq * 16);
        cp16(stg + d,         khB + g);
        cp16(stg + 8192 + d,  klB + g);
        cp16(stg + 16384 + d, vhB + g);
        cp16(stg + 24576 + d, vlB + g);
    }
    cp_commit();
}

__global__ __launch_bounds__(128, 3) void attn_tc_kernel()
{
    extern __shared__ char smem[];
    const uint32_t sb = smem_u32(smem);

    const int tid  = threadIdx.x;
    const int lane = tid & 31;
    const int warp = tid >> 5;
    const int bh = blockIdx.y;
    const int q0 = blockIdx.x * 64;

    const size_t hbase = (size_t)bh * Ss * Dd;
    const __nv_bfloat16* qhB = g_Qh + hbase;
    const __nv_bfloat16* qlB = g_Ql + hbase;
    const __nv_bfloat16* khB = g_Kh + hbase;
    const __nv_bfloat16* klB = g_Kl + hbase;
    const __nv_bfloat16* vhB = g_Vh + hbase;
    const __nv_bfloat16* vlB = g_Vl + hbase;

    const int lrow = lane & 15;
    const int lcb  = ((lane >> 4) * 8) * 2;

    // ---- Stage Q (64x64 hi/lo) into stage0 area, load A-frags ----
    #pragma unroll
    for (int it = 0; it < 4; it++) {
        int idx = tid + it * 128;
        int r = idx >> 3, cq = idx & 7;
        size_t g = (size_t)(q0 + r) * Dd + cq * 8;
        *(uint4*)(smem + swz(r, cq * 16))        = *(const uint4*)(qhB + g);
        *(uint4*)(smem + 8192 + swz(r, cq * 16)) = *(const uint4*)(qlB + g);
    }
    __syncthreads();
    uint32_t qh[4][4], ql[4][4];
    #pragma unroll
    for (int ks = 0; ks < 4; ks++) {
        uint32_t off = swz(warp * 16 + lrow, ks * 32 + lcb);
        ldsm4(qh[ks], sb + off);
        ldsm4(ql[ks], sb + 8192 + off);
    }
    __syncthreads();     // all warps done reading Q before cp.async overwrites

    const int ntiles = blockIdx.x + 1;
    attn_issue(sb, khB, klB, vhB, vlB, 0, tid);
    if (ntiles > 1) attn_issue(sb + AT_STAGE, khB, klB, vhB, vlB, 1, tid);
    else cp_commit();

    float o[8][4];
    #pragma unroll
    for (int nt = 0; nt < 8; nt++)
        #pragma unroll
        for (int r = 0; r < 4; r++) o[nt][r] = 0.f;
    float m0 = -1e30f, m1 = -1e30f, l0 = 0.f, l1 = 0.f;

    for (int kt = 0; kt < ntiles; kt++) {
        const uint32_t stg = sb + (kt & 1) * AT_STAGE;
        cp_wait1();
        __syncthreads();

        // ---- S = Q @ K^T (bf16x3) ----
        float s[8][4];
        #pragma unroll
        for (int nt = 0; nt < 8; nt++)
            #pragma unroll
            for (int r = 0; r < 4; r++) s[nt][r] = 0.f;

        #pragma unroll
        for (int kg = 0; kg < 4; kg++) {
            #pragma unroll
            for (int ks = 0; ks < 4; ks++) {
                uint32_t kh[4], kl[4];
                uint32_t off = swz(kg * 16 + lrow, ks * 32 + lcb);
                ldsm4(kh, stg + off);
                ldsm4(kl, stg + 8192 + off);
                mma_b2(s[2 * kg],     qh[ks], kh[0], kh[2]);
                mma_b2(s[2 * kg],     qh[ks], kl[0], kl[2]);
                mma_b2(s[2 * kg],     ql[ks], kh[0], kh[2]);
                mma_b2(s[2 * kg + 1], qh[ks], kh[1], kh[3]);
                mma_b2(s[2 * kg + 1], qh[ks], kl[1], kl[3]);
                mma_b2(s[2 * kg + 1], ql[ks], kh[1], kh[3]);
            }
        }

        #pragma unroll
        for (int nt = 0; nt < 8; nt++)
            #pragma unroll
            for (int r = 0; r < 4; r++) s[nt][r] *= 0.125f;

        if (kt == blockIdx.x) {
            int qloc0 = warp * 16 + (lane >> 2);
            int qloc1 = qloc0 + 8;
            #pragma unroll
            for (int nt = 0; nt < 8; nt++) {
                int key0 = nt * 8 + 2 * (lane & 3);
                if (key0     > qloc0) s[nt][0] = -10000.f;
                if (key0 + 1 > qloc0) s[nt][1] = -10000.f;
                if (key0     > qloc1) s[nt][2] = -10000.f;
                if (key0 + 1 > qloc1) s[nt][3] = -10000.f;
            }
        }

        // ---- online softmax ----
        float tm0 = -1e30f, tm1 = -1e30f;
        #pragma unroll
        for (int nt = 0; nt < 8; nt++) {
            tm0 = fmaxf(tm0, fmaxf(s[nt][0], s[nt][1]));
            tm1 = fmaxf(tm1, fmaxf(s[nt][2], s[nt][3]));
        }
        tm0 = fmaxf(tm0, __shfl_xor_sync(0xffffffffu, tm0, 1));
        tm0 = fmaxf(tm0, __shfl_xor_sync(0xffffffffu, tm0, 2));
        tm1 = fmaxf(tm1, __shfl_xor_sync(0xffffffffu, tm1, 1));
        tm1 = fmaxf(tm1, __shfl_xor_sync(0xffffffffu, tm1, 2));

        float mn0 = fmaxf(m0, tm0);
        float mn1 = fmaxf(m1, tm1);
        float sc0 = __expf(m0 - mn0);
        float sc1 = __expf(m1 - mn1);
        m0 = mn0; m1 = mn1;

        float rs0 = 0.f, rs1 = 0.f;
        #pragma unroll
        for (int nt = 0; nt < 8; nt++) {
            s[nt][0] = __expf(s[nt][0] - m0);
            s[nt][1] = __expf(s[nt][1] - m0);
            s[nt][2] = __expf(s[nt][2] - m1);
            s[nt][3] = __expf(s[nt][3] - m1);
            rs0 += s[nt][0] + s[nt][1];
            rs1 += s[nt][2] + s[nt][3];
        }
        rs0 += __shfl_xor_sync(0xffffffffu, rs0, 1);
        rs0 += __shfl_xor_sync(0xffffffffu, rs0, 2);
        rs1 += __shfl_xor_sync(0xffffffffu, rs1, 1);
        rs1 += __shfl_xor_sync(0xffffffffu, rs1, 2);
        l0 = l0 * sc0 + rs0;
        l1 = l1 * sc1 + rs1;

        #pragma unroll
        for (int nt = 0; nt < 8; nt++) {
            o[nt][0] *= sc0; o[nt][1] *= sc0;
            o[nt][2] *= sc1; o[nt][3] *= sc1;
        }

        // ---- pack P into A-fragments (hi/lo) ----
        uint32_t ph[4][4], pl[4][4];
        #pragma unroll
        for (int kk = 0; kk < 4; kk++) {
            int t0 = 2 * kk, t1 = 2 * kk + 1;
            ph[kk][0] = pack_hi(s[t0][0], s[t0][1]);
            ph[kk][1] = pack_hi(s[t0][2], s[t0][3]);
            ph[kk][2] = pack_hi(s[t1][0], s[t1][1]);
            ph[kk][3] = pack_hi(s[t1][2], s[t1][3]);
            pl[kk][0] = pack_lo(s[t0][0], s[t0][1]);
            pl[kk][1] = pack_lo(s[t0][2], s[t0][3]);
            pl[kk][2] = pack_lo(s[t1][0], s[t1][1]);
            pl[kk][3] = pack_lo(s[t1][2], s[t1][3]);
        }

        // ---- O += P @ V (bf16x3) ----
        #pragma unroll
        for (int kk = 0; kk < 4; kk++) {
            #pragma unroll
            for (int g = 0; g < 4; g++) {
                uint32_t vh[4], vl[4];
                uint32_t off = swz(kk * 16 + lrow, (g * 16) * 2 + lcb);
                ldsm4t(vh, stg + 16384 + off);
                ldsm4t(vl, stg + 24576 + off);
                mma_b2(o[2 * g],     ph[kk], vh[0], vh[1]);
                mma_b2(o[2 * g],     ph[kk], vl[0], vl[1]);
                mma_b2(o[2 * g],     pl[kk], vh[0], vh[1]);
                mma_b2(o[2 * g + 1], ph[kk], vh[2], vh[3]);
                mma_b2(o[2 * g + 1], ph[kk], vl[2], vl[3]);
                mma_b2(o[2 * g + 1], pl[kk], vh[2], vh[3]);
            }
        }

        __syncthreads();
        if (kt + 2 < ntiles)
            attn_issue(stg, khB, klB, vhB, vlB, kt + 2, tid);
        else
            cp_commit();
    }

    // ---- epilogue ----
    const float inv0 = 1.f / l0;
    const float inv1 = 1.f / l1;
    const int b = bh >> 4;
    const int h = bh & 15;
    const int row0 = b * Ss + q0 + warp * 16 + (lane >> 2);
    const int col0 = h * Dd + 2 * (lane & 3);
    #pragma unroll
    for (int nt = 0; nt < 8; nt++) {
        int c = col0 + nt * 8;
        float x0 = o[nt][0] * inv0, x1 = o[nt][1] * inv0;
        float y0 = o[nt][2] * inv1, y1 = o[nt][3] * inv1;
        size_t d0 = (size_t)row0 * Ee + c;
        size_t d1 = (size_t)(row0 + 8) * Ee + c;
        *(__nv_bfloat162*)&g_Ah[d0] = split_hi(x0, x1);
        *(__nv_bfloat162*)&g_Al[d0] = split_lo(x0, x1);
        *(__nv_bfloat162*)&g_Ah[d1] = split_hi(y0, y1);
        *(__nv_bfloat162*)&g_Al[d1] = split_lo(y0, y1);
    }
}

// ---------------------------------------------------------------------------
extern "C" void kernel_launch(void* const* d_in, const int* in_sizes, int n_in,
                              void* d_out, int out_size)
{
    const float* x  = (const float*)d_in[0];
    const float* Wq = (const float*)d_in[1];
    const float* bq = (const float*)d_in[2];
    const float* Wk = (const float*)d_in[3];
    const float* bk = (const float*)d_in[4];
    const float* Wv = (const float*)d_in[5];
    const float* bv = (const float*)d_in[6];
    const float* Wo = (const float*)d_in[7];
    const float* bo = (const float*)d_in[8];
    float* out = (float*)d_out;

    __nv_bfloat16 *Xh, *Xl;
    cudaGetSymbolAddress((void**)&Xh, g_Xh);
    cudaGetSymbolAddress((void**)&Xl, g_Xl);

    cudaFuncSetAttribute(gemm_qkv_kernel,
                         cudaFuncAttributeMaxDynamicSharedMemorySize, GP_SMEM);
    cudaFuncSetAttribute(gemm_out_kernel,
                         cudaFuncAttributeMaxDynamicSharedMemorySize, GP_SMEM);
    cudaFuncSetAttribute(attn_tc_kernel,
                         cudaFuncAttributeMaxDynamicSharedMemorySize, AT_SMEM);

    const int nX4 = MM * Ee / 4;
    split_kernel<<<(nX4 + 255) / 256, 256>>>(x, Xh, Xl, nX4);
    transpose_split_kernel<<<dim3(32, 32, 4), dim3(32, 8)>>>(Wq, Wk, Wv, Wo);

    gemm_qkv_kernel<<<dim3(16, 32, 3), 256, GP_SMEM>>>(bq, bk, bv);

    attn_tc_kernel<<<dim3(Ss / 64, Bb * Hh), 128, AT_SMEM>>>();

    gemm_out_kernel<<<dim3(16, 32), 256, GP_SMEM>>>(bo, out);
}